// round 1
// baseline (speedup 1.0000x reference)
#include <cuda_runtime.h>
#include <math.h>

#define S_LEN 2048
#define HID   4096
#define KVD   1024
#define NH    32
#define NKV   8
#define HD    128

// Scratch (device globals: allocation-free rule)
__device__ float g_Q[S_LEN * HID];
__device__ float g_K[S_LEN * KVD];
__device__ float g_V[S_LEN * KVD];
__device__ float g_AO[S_LEN * HID];

// ---------------------------------------------------------------------------
// SGEMM NT: C[M,N] = A[M,K] * B[N,K]^T   (A, B, C row-major)
// 128x128 block, BK=8, 256 threads, 8x8 micro-tile (split 4+4 to avoid conflicts)
// ---------------------------------------------------------------------------
__global__ __launch_bounds__(256, 2) void sgemm_nt_kernel(
    const float* __restrict__ A, const float* __restrict__ B,
    float* __restrict__ C, int M, int N, int K)
{
    __shared__ float As[8][128];
    __shared__ float Bs[8][128];

    const int tid = threadIdx.x;
    const int m0 = blockIdx.y * 128;
    const int n0 = blockIdx.x * 128;
    const int lr = tid >> 1;            // 0..127
    const int lc = (tid & 1) << 2;      // 0 or 4
    const int ty = tid >> 4;            // 0..15
    const int tx = tid & 15;            // 0..15

    const float* Ag = A + (size_t)(m0 + lr) * K + lc;
    const float* Bg = B + (size_t)(n0 + lr) * K + lc;

    float acc[8][8];
#pragma unroll
    for (int i = 0; i < 8; i++)
#pragma unroll
        for (int j = 0; j < 8; j++) acc[i][j] = 0.0f;

    float4 av = *(const float4*)Ag;
    float4 bv = *(const float4*)Bg;

    for (int k0 = 0; k0 < K; k0 += 8) {
        __syncthreads();
        As[lc + 0][lr] = av.x; As[lc + 1][lr] = av.y;
        As[lc + 2][lr] = av.z; As[lc + 3][lr] = av.w;
        Bs[lc + 0][lr] = bv.x; Bs[lc + 1][lr] = bv.y;
        Bs[lc + 2][lr] = bv.z; Bs[lc + 3][lr] = bv.w;
        __syncthreads();

        if (k0 + 8 < K) {
            av = *(const float4*)(Ag + k0 + 8);
            bv = *(const float4*)(Bg + k0 + 8);
        }

#pragma unroll
        for (int kk = 0; kk < 8; kk++) {
            float4 a0 = *(const float4*)&As[kk][ty * 4];
            float4 a1 = *(const float4*)&As[kk][ty * 4 + 64];
            float4 b0 = *(const float4*)&Bs[kk][tx * 4];
            float4 b1 = *(const float4*)&Bs[kk][tx * 4 + 64];
            float a[8] = {a0.x, a0.y, a0.z, a0.w, a1.x, a1.y, a1.z, a1.w};
            float b[8] = {b0.x, b0.y, b0.z, b0.w, b1.x, b1.y, b1.z, b1.w};
#pragma unroll
            for (int i = 0; i < 8; i++)
#pragma unroll
                for (int j = 0; j < 8; j++)
                    acc[i][j] += a[i] * b[j];
        }
    }

#pragma unroll
    for (int ih = 0; ih < 2; ih++) {
#pragma unroll
        for (int i = 0; i < 4; i++) {
            int row = m0 + ih * 64 + ty * 4 + i;
            float* Cp = C + (size_t)row * N + n0;
            int ai = ih * 4 + i;
            *(float4*)&Cp[tx * 4] =
                make_float4(acc[ai][0], acc[ai][1], acc[ai][2], acc[ai][3]);
            *(float4*)&Cp[64 + tx * 4] =
                make_float4(acc[ai][4], acc[ai][5], acc[ai][6], acc[ai][7]);
        }
    }
}

// ---------------------------------------------------------------------------
// RoPE (in place on g_Q, g_K). Double-precision sincos: matches the fp32
// reference to ~1e-4 worst case and is immune to fast-math sinf/cosf issues.
// ---------------------------------------------------------------------------
__global__ void rope_kernel(float* __restrict__ Q, float* __restrict__ Kb,
                            const int* __restrict__ pos)
{
    const int s = blockIdx.x;
    const int p = pos[s];
    const double ln_theta = 9.210340371976184; // ln(10000)

    for (int idx = threadIdx.x; idx < (NH + NKV) * 64; idx += blockDim.x) {
        float* buf;
        int stride, head, i;
        if (idx < NH * 64) {
            buf = Q; stride = HID; head = idx >> 6; i = idx & 63;
        } else {
            int t = idx - NH * 64;
            buf = Kb; stride = KVD; head = t >> 6; i = t & 63;
        }
        double inv = exp(-((double)(2 * i) / 128.0) * ln_theta);
        double ang = (double)p * inv;
        float c = (float)cos(ang);
        float sn = (float)sin(ang);
        float* base = buf + (size_t)s * stride + head * HD;
        float x0 = base[i];
        float x1 = base[i + 64];
        base[i]      = x0 * c - x1 * sn;
        base[i + 64] = x1 * c + x0 * sn;
    }
}

// ---------------------------------------------------------------------------
// Flash attention (fp32, causal, GQA 4:1).
// Grid: (S/64 q-blocks, 32 heads). 256 threads.
// smem: sQ[64][128], sK[64][132], sV[64][128], sP[64][64]  = 113 KB
// Per thread: 4 q-rows (ty*4+i), score cols tx+16j, O cols tx+16jj.
// ---------------------------------------------------------------------------
#define SKST 132

__global__ __launch_bounds__(256) void flash_kernel(
    const float* __restrict__ Qg, const float* __restrict__ Kg,
    const float* __restrict__ Vg, float* __restrict__ O)
{
    extern __shared__ float sm[];
    float* sQ = sm;                    // 64*128
    float* sK = sQ + 64 * 128;         // 64*132
    float* sV = sK + 64 * SKST;        // 64*128
    float* sP = sV + 64 * 128;         // 64*64

    const int h  = blockIdx.y;
    const int qb = gridDim.x - 1 - blockIdx.x;  // heavy blocks first
    const int kvh = h >> 2;
    const int tid = threadIdx.x;
    const int ty = tid >> 4;
    const int tx = tid & 15;
    const float scale = 0.08838834764831845f;   // 1/sqrt(128)

    // Load + pre-scale Q tile
#pragma unroll
    for (int it = 0; it < 8; it++) {
        int idx = tid + it * 256;
        int row = idx >> 5;
        int c4  = (idx & 31) << 2;
        float4 v = *(const float4*)&Qg[(size_t)(qb * 64 + row) * HID + h * HD + c4];
        v.x *= scale; v.y *= scale; v.z *= scale; v.w *= scale;
        *(float4*)&sQ[row * 128 + c4] = v;
    }

    float m[4], l[4], acc[4][8];
#pragma unroll
    for (int i = 0; i < 4; i++) {
        m[i] = -1e30f;
        l[i] = 0.0f;
#pragma unroll
        for (int j = 0; j < 8; j++) acc[i][j] = 0.0f;
    }

    for (int t = 0; t <= qb; t++) {
        __syncthreads();   // previous iter done with sK/sV/sP (and Q stores at t=0)
#pragma unroll
        for (int it = 0; it < 8; it++) {
            int idx = tid + it * 256;
            int row = idx >> 5;
            int c4  = (idx & 31) << 2;
            size_t gofs = (size_t)(t * 64 + row) * KVD + kvh * HD + c4;
            *(float4*)&sK[row * SKST + c4] = *(const float4*)&Kg[gofs];
            *(float4*)&sV[row * 128 + c4]  = *(const float4*)&Vg[gofs];
        }
        __syncthreads();

        // Scores: 4 rows (ty*4+i) x 4 cols (tx+16j)
        float sc[4][4];
#pragma unroll
        for (int i = 0; i < 4; i++)
#pragma unroll
            for (int j = 0; j < 4; j++) sc[i][j] = 0.0f;

        for (int k = 0; k < 128; k += 4) {
            float4 q0 = *(const float4*)&sQ[(ty * 4 + 0) * 128 + k];
            float4 q1 = *(const float4*)&sQ[(ty * 4 + 1) * 128 + k];
            float4 q2 = *(const float4*)&sQ[(ty * 4 + 2) * 128 + k];
            float4 q3 = *(const float4*)&sQ[(ty * 4 + 3) * 128 + k];
            float4 k0 = *(const float4*)&sK[(tx +  0) * SKST + k];
            float4 k1 = *(const float4*)&sK[(tx + 16) * SKST + k];
            float4 k2 = *(const float4*)&sK[(tx + 32) * SKST + k];
            float4 k3 = *(const float4*)&sK[(tx + 48) * SKST + k];
            float4 qa[4] = {q0, q1, q2, q3};
            float4 ka[4] = {k0, k1, k2, k3};
#pragma unroll
            for (int i = 0; i < 4; i++)
#pragma unroll
                for (int j = 0; j < 4; j++) {
                    sc[i][j] += qa[i].x * ka[j].x;
                    sc[i][j] += qa[i].y * ka[j].y;
                    sc[i][j] += qa[i].z * ka[j].z;
                    sc[i][j] += qa[i].w * ka[j].w;
                }
        }

        // Causal mask on diagonal tile
        if (t == qb) {
#pragma unroll
            for (int i = 0; i < 4; i++)
#pragma unroll
                for (int j = 0; j < 4; j++)
                    if (tx + 16 * j > ty * 4 + i) sc[i][j] = -1e30f;
        }

        // Online softmax (row stats reduced across the 16-lane tx group)
#pragma unroll
        for (int i = 0; i < 4; i++) {
            float mt = fmaxf(fmaxf(sc[i][0], sc[i][1]), fmaxf(sc[i][2], sc[i][3]));
#pragma unroll
            for (int off = 8; off > 0; off >>= 1)
                mt = fmaxf(mt, __shfl_xor_sync(0xffffffffu, mt, off, 16));
            float mn = fmaxf(m[i], mt);
            float alpha = __expf(m[i] - mn);
            m[i] = mn;

            float sum = 0.0f;
#pragma unroll
            for (int j = 0; j < 4; j++) {
                sc[i][j] = __expf(sc[i][j] - mn);
                sum += sc[i][j];
            }
#pragma unroll
            for (int off = 8; off > 0; off >>= 1)
                sum += __shfl_xor_sync(0xffffffffu, sum, off, 16);
            l[i] = l[i] * alpha + sum;

#pragma unroll
            for (int jj = 0; jj < 8; jj++) acc[i][jj] *= alpha;

            float* pr = &sP[(ty * 4 + i) * 64 + tx];
            pr[0]  = sc[i][0];
            pr[16] = sc[i][1];
            pr[32] = sc[i][2];
            pr[48] = sc[i][3];
        }
        __syncthreads();

        // PV: acc[i][jj] += sum_c P[row][c] * V[c][tx+16jj]
        for (int c = 0; c < 64; c++) {
            float p0 = sP[(ty * 4 + 0) * 64 + c];
            float p1 = sP[(ty * 4 + 1) * 64 + c];
            float p2 = sP[(ty * 4 + 2) * 64 + c];
            float p3 = sP[(ty * 4 + 3) * 64 + c];
            const float* vr = &sV[c * 128 + tx];
#pragma unroll
            for (int jj = 0; jj < 8; jj++) {
                float vv = vr[jj * 16];
                acc[0][jj] += p0 * vv;
                acc[1][jj] += p1 * vv;
                acc[2][jj] += p2 * vv;
                acc[3][jj] += p3 * vv;
            }
        }
    }

    // Epilogue: normalize and write to attn-out [S, 4096] (head-major cols)
#pragma unroll
    for (int i = 0; i < 4; i++) {
        float inv_l = 1.0f / l[i];
        size_t rbase = (size_t)(qb * 64 + ty * 4 + i) * HID + h * HD + tx;
#pragma unroll
        for (int jj = 0; jj < 8; jj++)
            O[rbase + jj * 16] = acc[i][jj] * inv_l;
    }
}

// ---------------------------------------------------------------------------
// kernel_launch
// ---------------------------------------------------------------------------
extern "C" void kernel_launch(void* const* d_in, const int* in_sizes, int n_in,
                              void* d_out, int out_size)
{
    const float* hidden = (const float*)d_in[0];
    const int*   pos    = (const int*)d_in[1];
    const float* Wq     = (const float*)d_in[2];
    const float* Wk     = (const float*)d_in[3];
    const float* Wv     = (const float*)d_in[4];
    const float* Wo     = (const float*)d_in[5];
    float* out = (float*)d_out;

    float *qp, *kp, *vp, *aop;
    cudaGetSymbolAddress((void**)&qp,  g_Q);
    cudaGetSymbolAddress((void**)&kp,  g_K);
    cudaGetSymbolAddress((void**)&vp,  g_V);
    cudaGetSymbolAddress((void**)&aop, g_AO);

    // QKV projections
    sgemm_nt_kernel<<<dim3(HID / 128, S_LEN / 128), 256>>>(hidden, Wq, qp, S_LEN, HID, HID);
    sgemm_nt_kernel<<<dim3(KVD / 128, S_LEN / 128), 256>>>(hidden, Wk, kp, S_LEN, KVD, HID);
    sgemm_nt_kernel<<<dim3(KVD / 128, S_LEN / 128), 256>>>(hidden, Wv, vp, S_LEN, KVD, HID);

    // RoPE
    rope_kernel<<<S_LEN, 256>>>(qp, kp, pos);

    // Flash attention
    const int smem_bytes = (64 * 128 + 64 * SKST + 64 * 128 + 64 * 64) * sizeof(float);
    cudaFuncSetAttribute(flash_kernel, cudaFuncAttributeMaxDynamicSharedMemorySize, smem_bytes);
    flash_kernel<<<dim3(S_LEN / 64, NH), 256, smem_bytes>>>(qp, kp, vp, aop);

    // Output projection
    sgemm_nt_kernel<<<dim3(HID / 128, S_LEN / 128), 256>>>(aop, Wo, out, S_LEN, HID, HID);
}

// round 3
// speedup vs baseline: 2.9635x; 2.9635x over previous
#include <cuda_runtime.h>
#include <cuda_bf16.h>
#include <math.h>
#include <stdint.h>

#define S_LEN 2048
#define HID   4096
#define KVD   1024
#define NH    32
#define NKV   8
#define HD    128

// ---------------- scratch (device globals; allocation-free rule) -----------
__device__ float g_Q[S_LEN * HID];
__device__ float g_K[S_LEN * KVD];
__device__ float g_V[S_LEN * KVD];
__device__ float g_AO[S_LEN * HID];
__device__ __nv_bfloat16 g_Ah[S_LEN * HID];     // activations hi
__device__ __nv_bfloat16 g_Al[S_LEN * HID];     // activations lo
__device__ __nv_bfloat16 g_Wh[HID * HID];       // weights hi (max 4096x4096)
__device__ __nv_bfloat16 g_Wl[HID * HID];       // weights lo
__device__ float g_cos[S_LEN * 64];
__device__ float g_sin[S_LEN * 64];

// ---------------- PTX helpers ----------------------------------------------
__device__ __forceinline__ uint32_t smem_u32(const void* p) {
    uint32_t a;
    asm("{ .reg .u64 t; cvta.to.shared.u64 t, %1; cvt.u32.u64 %0, t; }"
        : "=r"(a) : "l"(p));
    return a;
}
__device__ __forceinline__ void ldsm4(uint32_t* r, uint32_t addr) {
    asm volatile("ldmatrix.sync.aligned.m8n8.x4.shared.b16 {%0,%1,%2,%3}, [%4];"
                 : "=r"(r[0]), "=r"(r[1]), "=r"(r[2]), "=r"(r[3]) : "r"(addr));
}
__device__ __forceinline__ void ldsm2(uint32_t* r, uint32_t addr) {
    asm volatile("ldmatrix.sync.aligned.m8n8.x2.shared.b16 {%0,%1}, [%2];"
                 : "=r"(r[0]), "=r"(r[1]) : "r"(addr));
}
__device__ __forceinline__ void mma16816(float* d, const uint32_t* a,
                                         const uint32_t* b) {
    asm volatile(
        "mma.sync.aligned.m16n8k16.row.col.f32.bf16.bf16.f32 "
        "{%0,%1,%2,%3},{%4,%5,%6,%7},{%8,%9},{%0,%1,%2,%3};"
        : "+f"(d[0]), "+f"(d[1]), "+f"(d[2]), "+f"(d[3])
        : "r"(a[0]), "r"(a[1]), "r"(a[2]), "r"(a[3]), "r"(b[0]), "r"(b[1]));
}
__device__ __forceinline__ void cp_async16(uint32_t dst, const void* src) {
    asm volatile("cp.async.cg.shared.global [%0], [%1], 16;"
                 :: "r"(dst), "l"(src) : "memory");
}

// ---------------------------------------------------------------------------
// fp32 -> (bf16 hi, bf16 lo) split. n divisible by 4.
// ---------------------------------------------------------------------------
__global__ void split_bf16_kernel(const float* __restrict__ src,
                                  __nv_bfloat16* __restrict__ hi,
                                  __nv_bfloat16* __restrict__ lo, int n)
{
    int i = (blockIdx.x * blockDim.x + threadIdx.x) * 4;
    if (i >= n) return;
    float4 v = *(const float4*)(src + i);
    __nv_bfloat16 h0 = __float2bfloat16(v.x);
    __nv_bfloat16 h1 = __float2bfloat16(v.y);
    __nv_bfloat16 h2 = __float2bfloat16(v.z);
    __nv_bfloat16 h3 = __float2bfloat16(v.w);
    __nv_bfloat16 l0 = __float2bfloat16(v.x - __bfloat162float(h0));
    __nv_bfloat16 l1 = __float2bfloat16(v.y - __bfloat162float(h1));
    __nv_bfloat16 l2 = __float2bfloat16(v.z - __bfloat162float(h2));
    __nv_bfloat16 l3 = __float2bfloat16(v.w - __bfloat162float(h3));
    __nv_bfloat162* hp = (__nv_bfloat162*)(hi + i);
    __nv_bfloat162* lp = (__nv_bfloat162*)(lo + i);
    hp[0] = __nv_bfloat162(h0, h1); hp[1] = __nv_bfloat162(h2, h3);
    lp[0] = __nv_bfloat162(l0, l1); lp[1] = __nv_bfloat162(l2, l3);
}

// ---------------------------------------------------------------------------
// HMMA bf16x3 GEMM: C[2048, N] = A[2048, 4096] * B[N, 4096]^T  (fp32 out)
// CTA 128x128, 8 warps (warp tile 64x32), BK=32, double-buffered cp.async.
// smem rows padded to 40 bf16 (80B) -> conflict-free ldmatrix.
// ---------------------------------------------------------------------------
#define BK 32
#define ASTR 40                          // bf16 elems per smem row
#define TILE_BYTES (128 * ASTR * 2)      // 10240
#define STAGE_BYTES (4 * TILE_BYTES)     // 40960: Ah, Al, Bh, Bl
#define KTILES (HID / BK)                // 128

__global__ __launch_bounds__(256, 1) void gemm_mma_kernel(
    const __nv_bfloat16* __restrict__ Ah, const __nv_bfloat16* __restrict__ Al,
    const __nv_bfloat16* __restrict__ Bh, const __nv_bfloat16* __restrict__ Bl,
    float* __restrict__ C, int N)
{
    extern __shared__ char smem[];
    const uint32_t sb = smem_u32(smem);
    const int tid  = threadIdx.x;
    const int wid  = tid >> 5;
    const int lane = tid & 31;
    const int wm   = wid & 1;            // 2 m-tiles of 64
    const int wn   = wid >> 1;           // 4 n-tiles of 32
    const int m0   = blockIdx.y * 128;
    const int n0   = blockIdx.x * 128;

    const __nv_bfloat16* srcs[4] = {
        Ah + (size_t)m0 * HID, Al + (size_t)m0 * HID,
        Bh + (size_t)n0 * HID, Bl + (size_t)n0 * HID };

    auto load_stage = [&](int kt, int stage) {
        const int kc = kt * BK;
        const uint32_t sbase = sb + stage * STAGE_BYTES;
#pragma unroll
        for (int t = 0; t < 4; t++) {
            const __nv_bfloat16* src = srcs[t];
            const uint32_t tb = sbase + t * TILE_BYTES;
#pragma unroll
            for (int i = 0; i < 2; i++) {
                int idx = tid + i * 256;            // 0..511
                int row = idx >> 2;
                int kch = idx & 3;                  // 16B chunk within BK
                cp_async16(tb + (uint32_t)(row * 80 + kch * 16),
                           src + (size_t)row * HID + kc + kch * 8);
            }
        }
        asm volatile("cp.async.commit_group;" ::: "memory");
    };

    float d[4][4][4];
#pragma unroll
    for (int i = 0; i < 4; i++)
#pragma unroll
        for (int j = 0; j < 4; j++)
#pragma unroll
            for (int q = 0; q < 4; q++) d[i][j][q] = 0.0f;

    load_stage(0, 0);
    load_stage(1, 1);

    // ldmatrix lane addressing (bytes)
    const int la = lane & 15;
    const int a_k8 = (lane >> 4) << 3;       // 0 or 8 (k offset)
    const int lb = lane & 15;
    const int b_row8 = lb & 7;
    const int b_k8 = ((lb >> 3) & 1) << 3;

    for (int kt = 0; kt < KTILES; kt++) {
        if (kt + 2 < KTILES)
            asm volatile("cp.async.wait_group 1;" ::: "memory");
        else
            asm volatile("cp.async.wait_group 0;" ::: "memory");
        __syncthreads();

        const uint32_t sbase = sb + (kt & 1) * STAGE_BYTES;
        const uint32_t sAh = sbase;
        const uint32_t sAl = sbase + TILE_BYTES;
        const uint32_t sBh = sbase + 2 * TILE_BYTES;
        const uint32_t sBl = sbase + 3 * TILE_BYTES;

#pragma unroll
        for (int k16 = 0; k16 < 2; k16++) {
            const int kofA = k16 * 16 + a_k8;
            const int kofB = k16 * 16 + b_k8;

            uint32_t ah[4][4], al[4][4], bh[4][2], bl[4][2];
#pragma unroll
            for (int i = 0; i < 4; i++) {
                int arow = wm * 64 + i * 16 + la;
                uint32_t off = (uint32_t)(arow * ASTR + kofA) * 2;
                ldsm4(ah[i], sAh + off);
                ldsm4(al[i], sAl + off);
            }
#pragma unroll
            for (int j = 0; j < 4; j++) {
                int brow = wn * 32 + j * 8 + b_row8;
                uint32_t off = (uint32_t)(brow * ASTR + kofB) * 2;
                ldsm2(bh[j], sBh + off);
                ldsm2(bl[j], sBl + off);
            }
#pragma unroll
            for (int i = 0; i < 4; i++)
#pragma unroll
                for (int j = 0; j < 4; j++) {
                    mma16816(d[i][j], ah[i], bh[j]);
                    mma16816(d[i][j], ah[i], bl[j]);
                    mma16816(d[i][j], al[i], bh[j]);
                }
        }
        __syncthreads();
        if (kt + 2 < KTILES) load_stage(kt + 2, kt & 1);
    }

    // epilogue: fragment layout c0,c1 @ (lane/4, (lane%4)*2), c2,c3 @ +8 rows
#pragma unroll
    for (int i = 0; i < 4; i++) {
        int row = m0 + wm * 64 + i * 16 + (lane >> 2);
#pragma unroll
        for (int j = 0; j < 4; j++) {
            int col = n0 + wn * 32 + j * 8 + (lane & 3) * 2;
            *(float2*)&C[(size_t)row * N + col] = make_float2(d[i][j][0], d[i][j][1]);
            *(float2*)&C[(size_t)(row + 8) * N + col] = make_float2(d[i][j][2], d[i][j][3]);
        }
    }
}

// ---------------------------------------------------------------------------
// RoPE: fp64 table build (once) + fp32 apply
// ---------------------------------------------------------------------------
__global__ void rope_table_kernel(const int* __restrict__ pos)
{
    int idx = blockIdx.x * blockDim.x + threadIdx.x;   // s*64 + i
    int s = idx >> 6, i = idx & 63;
    double inv = exp(-((double)(2 * i) / 128.0) * 9.210340371976184);
    double ang = (double)pos[s] * inv;
    g_cos[idx] = (float)cos(ang);
    g_sin[idx] = (float)sin(ang);
}

__global__ void rope_apply_kernel(float* __restrict__ Q, float* __restrict__ Kb)
{
    const int s = blockIdx.x;
    for (int idx = threadIdx.x; idx < (NH + NKV) * 64; idx += blockDim.x) {
        float* buf; int stride, head, i;
        if (idx < NH * 64) { buf = Q;  stride = HID; head = idx >> 6; i = idx & 63; }
        else { int t = idx - NH * 64; buf = Kb; stride = KVD; head = t >> 6; i = t & 63; }
        float c  = g_cos[s * 64 + i];
        float sn = g_sin[s * 64 + i];
        float* base = buf + (size_t)s * stride + head * HD;
        float x0 = base[i];
        float x1 = base[i + 64];
        base[i]      = x0 * c - x1 * sn;
        base[i + 64] = x1 * c + x0 * sn;
    }
}

// ---------------------------------------------------------------------------
// Flash attention (fp32, causal, GQA 4:1)
// ---------------------------------------------------------------------------
#define SKST 132

__global__ __launch_bounds__(256) void flash_kernel(
    const float* __restrict__ Qg, const float* __restrict__ Kg,
    const float* __restrict__ Vg, float* __restrict__ O)
{
    extern __shared__ float sm[];
    float* sQ = sm;
    float* sK = sQ + 64 * 128;
    float* sV = sK + 64 * SKST;
    float* sP = sV + 64 * 128;

    const int h  = blockIdx.y;
    const int qb = gridDim.x - 1 - blockIdx.x;
    const int kvh = h >> 2;
    const int tid = threadIdx.x;
    const int ty = tid >> 4;
    const int tx = tid & 15;
    const float scale = 0.08838834764831845f;

#pragma unroll
    for (int it = 0; it < 8; it++) {
        int idx = tid + it * 256;
        int row = idx >> 5;
        int c4  = (idx & 31) << 2;
        float4 v = *(const float4*)&Qg[(size_t)(qb * 64 + row) * HID + h * HD + c4];
        v.x *= scale; v.y *= scale; v.z *= scale; v.w *= scale;
        *(float4*)&sQ[row * 128 + c4] = v;
    }

    float m[4], l[4], acc[4][8];
#pragma unroll
    for (int i = 0; i < 4; i++) {
        m[i] = -1e30f; l[i] = 0.0f;
#pragma unroll
        for (int j = 0; j < 8; j++) acc[i][j] = 0.0f;
    }

    for (int t = 0; t <= qb; t++) {
        __syncthreads();
#pragma unroll
        for (int it = 0; it < 8; it++) {
            int idx = tid + it * 256;
            int row = idx >> 5;
            int c4  = (idx & 31) << 2;
            size_t gofs = (size_t)(t * 64 + row) * KVD + kvh * HD + c4;
            *(float4*)&sK[row * SKST + c4] = *(const float4*)&Kg[gofs];
            *(float4*)&sV[row * 128 + c4]  = *(const float4*)&Vg[gofs];
        }
        __syncthreads();

        float sc[4][4];
#pragma unroll
        for (int i = 0; i < 4; i++)
#pragma unroll
            for (int j = 0; j < 4; j++) sc[i][j] = 0.0f;

        for (int k = 0; k < 128; k += 4) {
            float4 q0 = *(const float4*)&sQ[(ty * 4 + 0) * 128 + k];
            float4 q1 = *(const float4*)&sQ[(ty * 4 + 1) * 128 + k];
            float4 q2 = *(const float4*)&sQ[(ty * 4 + 2) * 128 + k];
            float4 q3 = *(const float4*)&sQ[(ty * 4 + 3) * 128 + k];
            float4 k0 = *(const float4*)&sK[(tx +  0) * SKST + k];
            float4 k1 = *(const float4*)&sK[(tx + 16) * SKST + k];
            float4 k2 = *(const float4*)&sK[(tx + 32) * SKST + k];
            float4 k3 = *(const float4*)&sK[(tx + 48) * SKST + k];
            float4 qa[4] = {q0, q1, q2, q3};
            float4 ka[4] = {k0, k1, k2, k3};
#pragma unroll
            for (int i = 0; i < 4; i++)
#pragma unroll
                for (int j = 0; j < 4; j++) {
                    sc[i][j] += qa[i].x * ka[j].x;
                    sc[i][j] += qa[i].y * ka[j].y;
                    sc[i][j] += qa[i].z * ka[j].z;
                    sc[i][j] += qa[i].w * ka[j].w;
                }
        }

        if (t == qb) {
#pragma unroll
            for (int i = 0; i < 4; i++)
#pragma unroll
                for (int j = 0; j < 4; j++)
                    if (tx + 16 * j > ty * 4 + i) sc[i][j] = -1e30f;
        }

#pragma unroll
        for (int i = 0; i < 4; i++) {
            float mt = fmaxf(fmaxf(sc[i][0], sc[i][1]), fmaxf(sc[i][2], sc[i][3]));
#pragma unroll
            for (int off = 8; off > 0; off >>= 1)
                mt = fmaxf(mt, __shfl_xor_sync(0xffffffffu, mt, off, 16));
            float mn = fmaxf(m[i], mt);
            float alpha = __expf(m[i] - mn);
            m[i] = mn;

            float sum = 0.0f;
#pragma unroll
            for (int j = 0; j < 4; j++) {
                sc[i][j] = __expf(sc[i][j] - mn);
                sum += sc[i][j];
            }
#pragma unroll
            for (int off = 8; off > 0; off >>= 1)
                sum += __shfl_xor_sync(0xffffffffu, sum, off, 16);
            l[i] = l[i] * alpha + sum;

#pragma unroll
            for (int jj = 0; jj < 8; jj++) acc[i][jj] *= alpha;

            float* pr = &sP[(ty * 4 + i) * 64 + tx];
            pr[0]  = sc[i][0];
            pr[16] = sc[i][1];
            pr[32] = sc[i][2];
            pr[48] = sc[i][3];
        }
        __syncthreads();

        for (int c = 0; c < 64; c++) {
            float p0 = sP[(ty * 4 + 0) * 64 + c];
            float p1 = sP[(ty * 4 + 1) * 64 + c];
            float p2 = sP[(ty * 4 + 2) * 64 + c];
            float p3 = sP[(ty * 4 + 3) * 64 + c];
            const float* vr = &sV[c * 128 + tx];
#pragma unroll
            for (int jj = 0; jj < 8; jj++) {
                float vv = vr[jj * 16];
                acc[0][jj] += p0 * vv;
                acc[1][jj] += p1 * vv;
                acc[2][jj] += p2 * vv;
                acc[3][jj] += p3 * vv;
            }
        }
    }

#pragma unroll
    for (int i = 0; i < 4; i++) {
        float inv_l = 1.0f / l[i];
        size_t rbase = (size_t)(qb * 64 + ty * 4 + i) * HID + h * HD + tx;
#pragma unroll
        for (int jj = 0; jj < 8; jj++)
            O[rbase + jj * 16] = acc[i][jj] * inv_l;
    }
}

// ---------------------------------------------------------------------------
// kernel_launch
// ---------------------------------------------------------------------------
extern "C" void kernel_launch(void* const* d_in, const int* in_sizes, int n_in,
                              void* d_out, int out_size)
{
    const float* hidden = (const float*)d_in[0];
    const int*   pos    = (const int*)d_in[1];
    const float* Wq     = (const float*)d_in[2];
    const float* Wk     = (const float*)d_in[3];
    const float* Wv     = (const float*)d_in[4];
    const float* Wo     = (const float*)d_in[5];
    float* out = (float*)d_out;

    float *qp, *kp, *vp, *aop;
    __nv_bfloat16 *ah, *al, *wh, *wl;
    cudaGetSymbolAddress((void**)&qp,  g_Q);
    cudaGetSymbolAddress((void**)&kp,  g_K);
    cudaGetSymbolAddress((void**)&vp,  g_V);
    cudaGetSymbolAddress((void**)&aop, g_AO);
    cudaGetSymbolAddress((void**)&ah,  g_Ah);
    cudaGetSymbolAddress((void**)&al,  g_Al);
    cudaGetSymbolAddress((void**)&wh,  g_Wh);
    cudaGetSymbolAddress((void**)&wl,  g_Wl);

    const int gemm_smem = 2 * STAGE_BYTES;   // 80 KB
    cudaFuncSetAttribute(gemm_mma_kernel,
                         cudaFuncAttributeMaxDynamicSharedMemorySize, gemm_smem);

    const int NA  = S_LEN * HID;     // 8.4M
    const int NWQ = HID * HID;       // 16.8M
    const int NWK = KVD * HID;       // 4.2M

    split_bf16_kernel<<<NA / 4 / 256, 256>>>(hidden, ah, al, NA);

    split_bf16_kernel<<<NWQ / 4 / 256, 256>>>(Wq, wh, wl, NWQ);
    gemm_mma_kernel<<<dim3(HID / 128, S_LEN / 128), 256, gemm_smem>>>(
        ah, al, wh, wl, qp, HID);

    split_bf16_kernel<<<NWK / 4 / 256, 256>>>(Wk, wh, wl, NWK);
    gemm_mma_kernel<<<dim3(KVD / 128, S_LEN / 128), 256, gemm_smem>>>(
        ah, al, wh, wl, kp, KVD);

    split_bf16_kernel<<<NWK / 4 / 256, 256>>>(Wv, wh, wl, NWK);
    gemm_mma_kernel<<<dim3(KVD / 128, S_LEN / 128), 256, gemm_smem>>>(
        ah, al, wh, wl, vp, KVD);

    rope_table_kernel<<<S_LEN * 64 / 256, 256>>>(pos);
    rope_apply_kernel<<<S_LEN, 256>>>(qp, kp);

    const int smem_bytes = (64 * 128 + 64 * SKST + 64 * 128 + 64 * 64) * sizeof(float);
    cudaFuncSetAttribute(flash_kernel,
                         cudaFuncAttributeMaxDynamicSharedMemorySize, smem_bytes);
    flash_kernel<<<dim3(S_LEN / 64, NH), 256, smem_bytes>>>(qp, kp, vp, aop);

    split_bf16_kernel<<<NA / 4 / 256, 256>>>(aop, ah, al, NA);
    split_bf16_kernel<<<NWQ / 4 / 256, 256>>>(Wo, wh, wl, NWQ);
    gemm_mma_kernel<<<dim3(HID / 128, S_LEN / 128), 256, gemm_smem>>>(
        ah, al, wh, wl, out, HID);
}

// round 4
// speedup vs baseline: 4.1660x; 1.4058x over previous
#include <cuda_runtime.h>
#include <cuda_bf16.h>
#include <math.h>
#include <stdint.h>

#define S_LEN 2048
#define HID   4096
#define KVD   1024
#define NH    32
#define NKV   8
#define HD    128

// ---------------- scratch (device globals; allocation-free rule) -----------
__device__ float g_Q[S_LEN * HID];
__device__ float g_K[S_LEN * KVD];
__device__ float g_V[S_LEN * KVD];
__device__ float g_AO[S_LEN * HID];
__device__ __nv_bfloat16 g_Ah[S_LEN * HID];
__device__ __nv_bfloat16 g_Al[S_LEN * HID];
__device__ __nv_bfloat16 g_Wh[HID * HID];
__device__ __nv_bfloat16 g_Wl[HID * HID];
__device__ __nv_bfloat16 g_Qh[S_LEN * HID];
__device__ __nv_bfloat16 g_Ql[S_LEN * HID];
__device__ __nv_bfloat16 g_Kh[S_LEN * KVD];
__device__ __nv_bfloat16 g_Kl[S_LEN * KVD];
__device__ __nv_bfloat16 g_Vh[S_LEN * KVD];
__device__ __nv_bfloat16 g_Vl[S_LEN * KVD];
__device__ float g_cos[S_LEN * 64];
__device__ float g_sin[S_LEN * 64];

// ---------------- PTX helpers ----------------------------------------------
__device__ __forceinline__ uint32_t smem_u32(const void* p) {
    uint32_t a;
    asm("{ .reg .u64 t; cvta.to.shared.u64 t, %1; cvt.u32.u64 %0, t; }"
        : "=r"(a) : "l"(p));
    return a;
}
__device__ __forceinline__ void ldsm4(uint32_t* r, uint32_t addr) {
    asm volatile("ldmatrix.sync.aligned.m8n8.x4.shared.b16 {%0,%1,%2,%3}, [%4];"
                 : "=r"(r[0]), "=r"(r[1]), "=r"(r[2]), "=r"(r[3]) : "r"(addr));
}
__device__ __forceinline__ void ldsm4t(uint32_t* r, uint32_t addr) {
    asm volatile("ldmatrix.sync.aligned.m8n8.x4.trans.shared.b16 {%0,%1,%2,%3}, [%4];"
                 : "=r"(r[0]), "=r"(r[1]), "=r"(r[2]), "=r"(r[3]) : "r"(addr));
}
__device__ __forceinline__ void ldsm2(uint32_t* r, uint32_t addr) {
    asm volatile("ldmatrix.sync.aligned.m8n8.x2.shared.b16 {%0,%1}, [%2];"
                 : "=r"(r[0]), "=r"(r[1]) : "r"(addr));
}
__device__ __forceinline__ void mma16816(float* d, const uint32_t* a,
                                         const uint32_t* b) {
    asm volatile(
        "mma.sync.aligned.m16n8k16.row.col.f32.bf16.bf16.f32 "
        "{%0,%1,%2,%3},{%4,%5,%6,%7},{%8,%9},{%0,%1,%2,%3};"
        : "+f"(d[0]), "+f"(d[1]), "+f"(d[2]), "+f"(d[3])
        : "r"(a[0]), "r"(a[1]), "r"(a[2]), "r"(a[3]), "r"(b[0]), "r"(b[1]));
}
__device__ __forceinline__ void cp_async16(uint32_t dst, const void* src) {
    asm volatile("cp.async.cg.shared.global [%0], [%1], 16;"
                 :: "r"(dst), "l"(src) : "memory");
}
__device__ __forceinline__ uint32_t pack_bf16(float x, float y) {
    uint32_t lo = (uint32_t)__bfloat16_as_ushort(__float2bfloat16(x));
    uint32_t hi = (uint32_t)__bfloat16_as_ushort(__float2bfloat16(y));
    return lo | (hi << 16);
}

// ---------------------------------------------------------------------------
// fp32 -> (bf16 hi, bf16 lo) split.
// ---------------------------------------------------------------------------
__global__ void split_bf16_kernel(const float* __restrict__ src,
                                  __nv_bfloat16* __restrict__ hi,
                                  __nv_bfloat16* __restrict__ lo, int n)
{
    int i = (blockIdx.x * blockDim.x + threadIdx.x) * 4;
    if (i >= n) return;
    float4 v = *(const float4*)(src + i);
    __nv_bfloat16 h0 = __float2bfloat16(v.x);
    __nv_bfloat16 h1 = __float2bfloat16(v.y);
    __nv_bfloat16 h2 = __float2bfloat16(v.z);
    __nv_bfloat16 h3 = __float2bfloat16(v.w);
    __nv_bfloat16 l0 = __float2bfloat16(v.x - __bfloat162float(h0));
    __nv_bfloat16 l1 = __float2bfloat16(v.y - __bfloat162float(h1));
    __nv_bfloat16 l2 = __float2bfloat16(v.z - __bfloat162float(h2));
    __nv_bfloat16 l3 = __float2bfloat16(v.w - __bfloat162float(h3));
    __nv_bfloat162* hp = (__nv_bfloat162*)(hi + i);
    __nv_bfloat162* lp = (__nv_bfloat162*)(lo + i);
    hp[0] = __nv_bfloat162(h0, h1); hp[1] = __nv_bfloat162(h2, h3);
    lp[0] = __nv_bfloat162(l0, l1); lp[1] = __nv_bfloat162(l2, l3);
}

// ---------------------------------------------------------------------------
// HMMA bf16x3 GEMM: C[2048, N] = A[2048, 4096] * B[N, 4096]^T  (fp32 out)
// ---------------------------------------------------------------------------
#define BK 32
#define ASTR 40
#define TILE_BYTES (128 * ASTR * 2)
#define STAGE_BYTES (4 * TILE_BYTES)
#define KTILES (HID / BK)

__global__ __launch_bounds__(256, 1) void gemm_mma_kernel(
    const __nv_bfloat16* __restrict__ Ah, const __nv_bfloat16* __restrict__ Al,
    const __nv_bfloat16* __restrict__ Bh, const __nv_bfloat16* __restrict__ Bl,
    float* __restrict__ C, int N)
{
    extern __shared__ char smem[];
    const uint32_t sb = smem_u32(smem);
    const int tid  = threadIdx.x;
    const int wid  = tid >> 5;
    const int lane = tid & 31;
    const int wm   = wid & 1;
    const int wn   = wid >> 1;
    const int m0   = blockIdx.y * 128;
    const int n0   = blockIdx.x * 128;

    const __nv_bfloat16* srcs[4] = {
        Ah + (size_t)m0 * HID, Al + (size_t)m0 * HID,
        Bh + (size_t)n0 * HID, Bl + (size_t)n0 * HID };

    auto load_stage = [&](int kt, int stage) {
        const int kc = kt * BK;
        const uint32_t sbase = sb + stage * STAGE_BYTES;
#pragma unroll
        for (int t = 0; t < 4; t++) {
            const __nv_bfloat16* src = srcs[t];
            const uint32_t tb = sbase + t * TILE_BYTES;
#pragma unroll
            for (int i = 0; i < 2; i++) {
                int idx = tid + i * 256;
                int row = idx >> 2;
                int kch = idx & 3;
                cp_async16(tb + (uint32_t)(row * 80 + kch * 16),
                           src + (size_t)row * HID + kc + kch * 8);
            }
        }
        asm volatile("cp.async.commit_group;" ::: "memory");
    };

    float d[4][4][4];
#pragma unroll
    for (int i = 0; i < 4; i++)
#pragma unroll
        for (int j = 0; j < 4; j++)
#pragma unroll
            for (int q = 0; q < 4; q++) d[i][j][q] = 0.0f;

    load_stage(0, 0);
    load_stage(1, 1);

    const int la = lane & 15;
    const int a_k8 = (lane >> 4) << 3;
    const int b_row8 = lane & 7;
    const int b_k8 = ((lane >> 3) & 1) << 3;

    for (int kt = 0; kt < KTILES; kt++) {
        if (kt + 2 < KTILES)
            asm volatile("cp.async.wait_group 1;" ::: "memory");
        else
            asm volatile("cp.async.wait_group 0;" ::: "memory");
        __syncthreads();

        const uint32_t sbase = sb + (kt & 1) * STAGE_BYTES;
        const uint32_t sAh = sbase;
        const uint32_t sAl = sbase + TILE_BYTES;
        const uint32_t sBh = sbase + 2 * TILE_BYTES;
        const uint32_t sBl = sbase + 3 * TILE_BYTES;

#pragma unroll
        for (int k16 = 0; k16 < 2; k16++) {
            const int kofA = k16 * 16 + a_k8;
            const int kofB = k16 * 16 + b_k8;

            uint32_t ah[4][4], al[4][4], bh[4][2], bl[4][2];
#pragma unroll
            for (int i = 0; i < 4; i++) {
                int arow = wm * 64 + i * 16 + la;
                uint32_t off = (uint32_t)(arow * ASTR + kofA) * 2;
                ldsm4(ah[i], sAh + off);
                ldsm4(al[i], sAl + off);
            }
#pragma unroll
            for (int j = 0; j < 4; j++) {
                int brow = wn * 32 + j * 8 + b_row8;
                uint32_t off = (uint32_t)(brow * ASTR + kofB) * 2;
                ldsm2(bh[j], sBh + off);
                ldsm2(bl[j], sBl + off);
            }
#pragma unroll
            for (int i = 0; i < 4; i++)
#pragma unroll
                for (int j = 0; j < 4; j++) {
                    mma16816(d[i][j], ah[i], bh[j]);
                    mma16816(d[i][j], ah[i], bl[j]);
                    mma16816(d[i][j], al[i], bh[j]);
                }
        }
        __syncthreads();
        if (kt + 2 < KTILES) load_stage(kt + 2, kt & 1);
    }

#pragma unroll
    for (int i = 0; i < 4; i++) {
        int row = m0 + wm * 64 + i * 16 + (lane >> 2);
#pragma unroll
        for (int j = 0; j < 4; j++) {
            int col = n0 + wn * 32 + j * 8 + (lane & 3) * 2;
            *(float2*)&C[(size_t)row * N + col] = make_float2(d[i][j][0], d[i][j][1]);
            *(float2*)&C[(size_t)(row + 8) * N + col] = make_float2(d[i][j][2], d[i][j][3]);
        }
    }
}

// ---------------------------------------------------------------------------
// RoPE table (fp64, once)
// ---------------------------------------------------------------------------
__global__ void rope_table_kernel(const int* __restrict__ pos)
{
    int idx = blockIdx.x * blockDim.x + threadIdx.x;
    int s = idx >> 6, i = idx & 63;
    double inv = exp(-((double)(2 * i) / 128.0) * 9.210340371976184);
    double ang = (double)pos[s] * inv;
    g_cos[idx] = (float)cos(ang);
    g_sin[idx] = (float)sin(ang);
}

// ---------------------------------------------------------------------------
// Fused RoPE + scale(Q only) + bf16 hi/lo split for Q and K.
// ---------------------------------------------------------------------------
__global__ void rope_split_kernel()
{
    const int s = blockIdx.x;
    const float qscale = 0.08838834764831845f;  // 1/sqrt(128)
    for (int idx = threadIdx.x; idx < (NH + NKV) * 64; idx += blockDim.x) {
        const float* src; __nv_bfloat16 *dh, *dl;
        int stride, head, i; float scale;
        if (idx < NH * 64) {
            src = g_Q; dh = g_Qh; dl = g_Ql; stride = HID;
            head = idx >> 6; i = idx & 63; scale = qscale;
        } else {
            int t = idx - NH * 64;
            src = g_K; dh = g_Kh; dl = g_Kl; stride = KVD;
            head = t >> 6; i = t & 63; scale = 1.0f;
        }
        float c  = g_cos[s * 64 + i];
        float sn = g_sin[s * 64 + i];
        size_t base = (size_t)s * stride + head * HD;
        float x0 = src[base + i];
        float x1 = src[base + i + 64];
        float y0 = (x0 * c - x1 * sn) * scale;
        float y1 = (x1 * c + x0 * sn) * scale;
        __nv_bfloat16 h0 = __float2bfloat16(y0);
        __nv_bfloat16 h1 = __float2bfloat16(y1);
        dh[base + i]      = h0;
        dh[base + i + 64] = h1;
        dl[base + i]      = __float2bfloat16(y0 - __bfloat162float(h0));
        dl[base + i + 64] = __float2bfloat16(y1 - __bfloat162float(h1));
    }
}

// ---------------------------------------------------------------------------
// Tensor-core flash attention (bf16x3 QK and PV, fp32 softmax), causal, GQA.
// CTA: 128 q-rows x 1 head. 8 warps, warp = 16 q-rows. KV tile = 64.
// smem rows padded to 136 bf16 elems (272B): bank-group step 17%8=1 -> no LDSM conflicts.
// ---------------------------------------------------------------------------
#define QSTR 136
#define FTILE (64 * QSTR * 2)       // 17408 B (one 64x128 bf16 subtile)
#define FSTAGE (4 * FTILE)          // 69632: Kh,Kl,Vh,Vl
#define FQOFF  (2 * FSTAGE)         // 139264
#define FQSZ   (128 * QSTR * 2)     // 34816
#define FSMEM  (FQOFF + 2 * FQSZ)   // 208896

__global__ __launch_bounds__(256, 1) void flash_mma_kernel(
    const __nv_bfloat16* __restrict__ Qh, const __nv_bfloat16* __restrict__ Ql,
    const __nv_bfloat16* __restrict__ Kh, const __nv_bfloat16* __restrict__ Kl,
    const __nv_bfloat16* __restrict__ Vh, const __nv_bfloat16* __restrict__ Vl,
    float* __restrict__ O)
{
    extern __shared__ char smem[];
    const uint32_t sb = smem_u32(smem);
    const int tid = threadIdx.x;
    const int lane = tid & 31;
    const int w = tid >> 5;
    const int h = blockIdx.x;
    const int qb = gridDim.y - 1 - blockIdx.y;   // heavy q-blocks first
    const int kvh = h >> 2;
    const int ntiles = 2 * (qb + 1);

    const __nv_bfloat16* qsrc[2] = {
        Qh + (size_t)(qb * 128) * HID + h * HD,
        Ql + (size_t)(qb * 128) * HID + h * HD };
    const __nv_bfloat16* tsrc[4] = {
        Kh + (size_t)kvh * HD, Kl + (size_t)kvh * HD,
        Vh + (size_t)kvh * HD, Vl + (size_t)kvh * HD };

    // Q tiles (Qh, Ql)
#pragma unroll
    for (int s2 = 0; s2 < 2; s2++)
#pragma unroll
        for (int i = 0; i < 8; i++) {
            int idx = tid + i * 256;            // 0..2047
            int row = idx >> 4, ch = idx & 15;
            cp_async16(sb + FQOFF + s2 * FQSZ + (uint32_t)(row * 272 + ch * 16),
                       qsrc[s2] + (size_t)row * HID + ch * 8);
        }
    asm volatile("cp.async.commit_group;" ::: "memory");

    auto load_tile = [&](int t, int buf) {
#pragma unroll
        for (int sub = 0; sub < 4; sub++) {
            const __nv_bfloat16* src = tsrc[sub];
            const uint32_t tb = sb + buf * FSTAGE + sub * FTILE;
#pragma unroll
            for (int i = 0; i < 4; i++) {
                int idx = tid + i * 256;        // 0..1023
                int row = idx >> 4, ch = idx & 15;
                cp_async16(tb + (uint32_t)(row * 272 + ch * 16),
                           src + (size_t)(t * 64 + row) * KVD + ch * 8);
            }
        }
        asm volatile("cp.async.commit_group;" ::: "memory");
    };

    load_tile(0, 0);
    if (ntiles > 1) load_tile(1, 1);

    float m[2] = {-1e30f, -1e30f}, l[2] = {0.0f, 0.0f};
    float o[16][4];
#pragma unroll
    for (int j = 0; j < 16; j++)
#pragma unroll
        for (int q = 0; q < 4; q++) o[j][q] = 0.0f;

    const int la = lane & 15;
    const int a_k8 = (lane >> 4) << 3;
    const int b_row8 = lane & 7;
    const int b_k8 = ((lane >> 3) & 1) << 3;
    const int r0 = lane >> 2;
    const int qrow0 = qb * 128 + w * 16;

    const uint32_t sQh = sb + FQOFF;
    const uint32_t sQl = sQh + FQSZ;

    for (int t = 0; t < ntiles; t++) {
        if (t + 1 < ntiles)
            asm volatile("cp.async.wait_group 1;" ::: "memory");
        else
            asm volatile("cp.async.wait_group 0;" ::: "memory");
        __syncthreads();

        const uint32_t stg = sb + (t & 1) * FSTAGE;
        const uint32_t sKh = stg, sKl = stg + FTILE;
        const uint32_t sVh = stg + 2 * FTILE, sVl = stg + 3 * FTILE;

        const bool skip = (qrow0 + 15) < t * 64;   // fully masked for this warp
        if (!skip) {
            // ---- scores S = Q K^T (3-term split) ----
            float sc[8][4];
#pragma unroll
            for (int nt = 0; nt < 8; nt++)
#pragma unroll
                for (int q = 0; q < 4; q++) sc[nt][q] = 0.0f;

#pragma unroll
            for (int ks = 0; ks < 8; ks++) {
                uint32_t aoff = (uint32_t)((w * 16 + la) * QSTR + ks * 16 + a_k8) * 2;
                uint32_t aqh[4], aql[4];
                ldsm4(aqh, sQh + aoff);
                ldsm4(aql, sQl + aoff);
#pragma unroll
                for (int nt = 0; nt < 8; nt++) {
                    uint32_t boff = (uint32_t)((nt * 8 + b_row8) * QSTR + ks * 16 + b_k8) * 2;
                    uint32_t bh[2], bl[2];
                    ldsm2(bh, sKh + boff);
                    ldsm2(bl, sKl + boff);
                    mma16816(sc[nt], aqh, bh);
                    mma16816(sc[nt], aqh, bl);
                    mma16816(sc[nt], aql, bh);
                }
            }

            // ---- causal mask (diagonal band only) ----
            if (t * 64 + 63 > qrow0) {
#pragma unroll
                for (int nt = 0; nt < 8; nt++)
#pragma unroll
                    for (int e = 0; e < 4; e++) {
                        int col = t * 64 + nt * 8 + (lane & 3) * 2 + (e & 1);
                        int row = qrow0 + r0 + ((e >> 1) << 3);
                        if (col > row) sc[nt][e] = -1e30f;
                    }
            }

            // ---- online softmax ----
#pragma unroll
            for (int rr = 0; rr < 2; rr++) {
                float mt = -1e30f;
#pragma unroll
                for (int nt = 0; nt < 8; nt++)
                    mt = fmaxf(mt, fmaxf(sc[nt][rr * 2], sc[nt][rr * 2 + 1]));
                mt = fmaxf(mt, __shfl_xor_sync(0xffffffffu, mt, 1));
                mt = fmaxf(mt, __shfl_xor_sync(0xffffffffu, mt, 2));
                float mn = fmaxf(m[rr], mt);
                float alpha = __expf(m[rr] - mn);
                m[rr] = mn;
                float sum = 0.0f;
#pragma unroll
                for (int nt = 0; nt < 8; nt++) {
                    float p0 = __expf(sc[nt][rr * 2]     - mn);
                    float p1 = __expf(sc[nt][rr * 2 + 1] - mn);
                    sc[nt][rr * 2] = p0; sc[nt][rr * 2 + 1] = p1;
                    sum += p0 + p1;
                }
                sum += __shfl_xor_sync(0xffffffffu, sum, 1);
                sum += __shfl_xor_sync(0xffffffffu, sum, 2);
                l[rr] = l[rr] * alpha + sum;
#pragma unroll
                for (int j = 0; j < 16; j++) {
                    o[j][rr * 2]     *= alpha;
                    o[j][rr * 2 + 1] *= alpha;
                }
            }

            // ---- pack P hi/lo directly into A fragments ----
            uint32_t ph[4][4], pl[4][4];
#pragma unroll
            for (int ks2 = 0; ks2 < 4; ks2++)
#pragma unroll
                for (int half = 0; half < 2; half++) {
                    int nt = 2 * ks2 + half;
#pragma unroll
                    for (int rr = 0; rr < 2; rr++) {
                        float p0 = sc[nt][rr * 2], p1 = sc[nt][rr * 2 + 1];
                        __nv_bfloat16 h0 = __float2bfloat16(p0);
                        __nv_bfloat16 h1 = __float2bfloat16(p1);
                        ph[ks2][half * 2 + rr] =
                            (uint32_t)__bfloat16_as_ushort(h0) |
                            ((uint32_t)__bfloat16_as_ushort(h1) << 16);
                        pl[ks2][half * 2 + rr] =
                            pack_bf16(p0 - __bfloat162float(h0),
                                      p1 - __bfloat162float(h1));
                    }
                }

            // ---- O += P V (3-term split) ----
#pragma unroll
            for (int ks2 = 0; ks2 < 4; ks2++) {
#pragma unroll
                for (int np = 0; np < 8; np++) {
                    uint32_t voff = (uint32_t)((ks2 * 16 + la) * QSTR + np * 16 + a_k8) * 2;
                    uint32_t vh[4], vl[4];
                    ldsm4t(vh, sVh + voff);
                    ldsm4t(vl, sVl + voff);
                    mma16816(o[2 * np],     ph[ks2], vh);
                    mma16816(o[2 * np],     ph[ks2], vl);
                    mma16816(o[2 * np],     pl[ks2], vh);
                    mma16816(o[2 * np + 1], ph[ks2], vh + 2);
                    mma16816(o[2 * np + 1], ph[ks2], vl + 2);
                    mma16816(o[2 * np + 1], pl[ks2], vh + 2);
                }
            }
        }
        __syncthreads();
        if (t + 2 < ntiles) load_tile(t + 2, t & 1);
    }

    // ---- epilogue ----
#pragma unroll
    for (int rr = 0; rr < 2; rr++) {
        float inv = 1.0f / l[rr];
        int grow = qrow0 + r0 + rr * 8;
#pragma unroll
        for (int j = 0; j < 16; j++) {
            int col = h * HD + j * 8 + (lane & 3) * 2;
            *(float2*)&O[(size_t)grow * HID + col] =
                make_float2(o[j][rr * 2] * inv, o[j][rr * 2 + 1] * inv);
        }
    }
}

// ---------------------------------------------------------------------------
// kernel_launch
// ---------------------------------------------------------------------------
extern "C" void kernel_launch(void* const* d_in, const int* in_sizes, int n_in,
                              void* d_out, int out_size)
{
    const float* hidden = (const float*)d_in[0];
    const int*   pos    = (const int*)d_in[1];
    const float* Wq     = (const float*)d_in[2];
    const float* Wk     = (const float*)d_in[3];
    const float* Wv     = (const float*)d_in[4];
    const float* Wo     = (const float*)d_in[5];
    float* out = (float*)d_out;

    float *qp, *kp, *vp, *aop;
    __nv_bfloat16 *ah, *al, *wh, *wl, *qhp, *qlp, *khp, *klp, *vhp, *vlp;
    cudaGetSymbolAddress((void**)&qp,  g_Q);
    cudaGetSymbolAddress((void**)&kp,  g_K);
    cudaGetSymbolAddress((void**)&vp,  g_V);
    cudaGetSymbolAddress((void**)&aop, g_AO);
    cudaGetSymbolAddress((void**)&ah,  g_Ah);
    cudaGetSymbolAddress((void**)&al,  g_Al);
    cudaGetSymbolAddress((void**)&wh,  g_Wh);
    cudaGetSymbolAddress((void**)&wl,  g_Wl);
    cudaGetSymbolAddress((void**)&qhp, g_Qh);
    cudaGetSymbolAddress((void**)&qlp, g_Ql);
    cudaGetSymbolAddress((void**)&khp, g_Kh);
    cudaGetSymbolAddress((void**)&klp, g_Kl);
    cudaGetSymbolAddress((void**)&vhp, g_Vh);
    cudaGetSymbolAddress((void**)&vlp, g_Vl);

    const int gemm_smem = 2 * STAGE_BYTES;
    cudaFuncSetAttribute(gemm_mma_kernel,
                         cudaFuncAttributeMaxDynamicSharedMemorySize, gemm_smem);
    cudaFuncSetAttribute(flash_mma_kernel,
                         cudaFuncAttributeMaxDynamicSharedMemorySize, FSMEM);

    const int NA  = S_LEN * HID;
    const int NWQ = HID * HID;
    const int NWK = KVD * HID;

    split_bf16_kernel<<<NA / 4 / 256, 256>>>(hidden, ah, al, NA);

    split_bf16_kernel<<<NWQ / 4 / 256, 256>>>(Wq, wh, wl, NWQ);
    gemm_mma_kernel<<<dim3(HID / 128, S_LEN / 128), 256, gemm_smem>>>(
        ah, al, wh, wl, qp, HID);

    split_bf16_kernel<<<NWK / 4 / 256, 256>>>(Wk, wh, wl, NWK);
    gemm_mma_kernel<<<dim3(KVD / 128, S_LEN / 128), 256, gemm_smem>>>(
        ah, al, wh, wl, kp, KVD);

    split_bf16_kernel<<<NWK / 4 / 256, 256>>>(Wv, wh, wl, NWK);
    gemm_mma_kernel<<<dim3(KVD / 128, S_LEN / 128), 256, gemm_smem>>>(
        ah, al, wh, wl, vp, KVD);

    rope_table_kernel<<<S_LEN * 64 / 256, 256>>>(pos);
    rope_split_kernel<<<S_LEN, 256>>>();
    split_bf16_kernel<<<S_LEN * KVD / 4 / 256, 256>>>(vp, vhp, vlp, S_LEN * KVD);

    flash_mma_kernel<<<dim3(NH, S_LEN / 128), 256, FSMEM>>>(
        qhp, qlp, khp, klp, vhp, vlp, aop);

    split_bf16_kernel<<<NA / 4 / 256, 256>>>(aop, ah, al, NA);
    split_bf16_kernel<<<NWQ / 4 / 256, 256>>>(Wo, wh, wl, NWQ);
    gemm_mma_kernel<<<dim3(HID / 128, S_LEN / 128), 256, gemm_smem>>>(
        ah, al, wh, wl, out, HID);
}

// round 6
// speedup vs baseline: 4.6263x; 1.1105x over previous
#include <cuda_runtime.h>
#include <cuda_bf16.h>
#include <math.h>
#include <stdint.h>

#define S_LEN 2048
#define HID   4096
#define KVD   1024
#define NH    32
#define NKV   8
#define HD    128

// ---------------- scratch (device globals; allocation-free rule) -----------
__device__ float g_Q[S_LEN * HID];
__device__ float g_K[S_LEN * KVD];
__device__ float g_V[S_LEN * KVD];
__device__ float g_AO[S_LEN * HID];
__device__ __nv_bfloat16 g_Ah[S_LEN * HID];
__device__ __nv_bfloat16 g_Al[S_LEN * HID];
__device__ __nv_bfloat16 g_Wh[HID * HID];
__device__ __nv_bfloat16 g_Wl[HID * HID];
__device__ __nv_bfloat16 g_Wh2[KVD * HID];
__device__ __nv_bfloat16 g_Wl2[KVD * HID];
__device__ __nv_bfloat16 g_Qh[S_LEN * HID];
__device__ __nv_bfloat16 g_Ql[S_LEN * HID];
__device__ __nv_bfloat16 g_Kh[S_LEN * KVD];
__device__ __nv_bfloat16 g_Kl[S_LEN * KVD];
__device__ __nv_bfloat16 g_Vh[S_LEN * KVD];
__device__ __nv_bfloat16 g_Vl[S_LEN * KVD];
__device__ float g_cos[S_LEN * 64];
__device__ float g_sin[S_LEN * 64];

// ---------------- PTX helpers ----------------------------------------------
__device__ __forceinline__ uint32_t smem_u32(const void* p) {
    uint32_t a;
    asm("{ .reg .u64 t; cvta.to.shared.u64 t, %1; cvt.u32.u64 %0, t; }"
        : "=r"(a) : "l"(p));
    return a;
}
__device__ __forceinline__ void ldsm4(uint32_t* r, uint32_t addr) {
    asm volatile("ldmatrix.sync.aligned.m8n8.x4.shared.b16 {%0,%1,%2,%3}, [%4];"
                 : "=r"(r[0]), "=r"(r[1]), "=r"(r[2]), "=r"(r[3]) : "r"(addr));
}
__device__ __forceinline__ void ldsm4t(uint32_t* r, uint32_t addr) {
    asm volatile("ldmatrix.sync.aligned.m8n8.x4.trans.shared.b16 {%0,%1,%2,%3}, [%4];"
                 : "=r"(r[0]), "=r"(r[1]), "=r"(r[2]), "=r"(r[3]) : "r"(addr));
}
__device__ __forceinline__ void mma16816(float* d, const uint32_t* a,
                                         const uint32_t* b) {
    asm volatile(
        "mma.sync.aligned.m16n8k16.row.col.f32.bf16.bf16.f32 "
        "{%0,%1,%2,%3},{%4,%5,%6,%7},{%8,%9},{%0,%1,%2,%3};"
        : "+f"(d[0]), "+f"(d[1]), "+f"(d[2]), "+f"(d[3])
        : "r"(a[0]), "r"(a[1]), "r"(a[2]), "r"(a[3]), "r"(b[0]), "r"(b[1]));
}
__device__ __forceinline__ void cp_async16(uint32_t dst, const void* src) {
    asm volatile("cp.async.cg.shared.global [%0], [%1], 16;"
                 :: "r"(dst), "l"(src) : "memory");
}
__device__ __forceinline__ uint32_t pack_bf16(float x, float y) {
    uint32_t lo = (uint32_t)__bfloat16_as_ushort(__float2bfloat16(x));
    uint32_t hi = (uint32_t)__bfloat16_as_ushort(__float2bfloat16(y));
    return lo | (hi << 16);
}

// ---------------------------------------------------------------------------
// fp32 -> (bf16 hi, bf16 lo) split.
// ---------------------------------------------------------------------------
__global__ void split_bf16_kernel(const float* __restrict__ src,
                                  __nv_bfloat16* __restrict__ hi,
                                  __nv_bfloat16* __restrict__ lo, int n)
{
    int i = (blockIdx.x * blockDim.x + threadIdx.x) * 4;
    if (i >= n) return;
    float4 v = *(const float4*)(src + i);
    __nv_bfloat16 h0 = __float2bfloat16(v.x);
    __nv_bfloat16 h1 = __float2bfloat16(v.y);
    __nv_bfloat16 h2 = __float2bfloat16(v.z);
    __nv_bfloat16 h3 = __float2bfloat16(v.w);
    __nv_bfloat16 l0 = __float2bfloat16(v.x - __bfloat162float(h0));
    __nv_bfloat16 l1 = __float2bfloat16(v.y - __bfloat162float(h1));
    __nv_bfloat16 l2 = __float2bfloat16(v.z - __bfloat162float(h2));
    __nv_bfloat16 l3 = __float2bfloat16(v.w - __bfloat162float(h3));
    __nv_bfloat162* hp = (__nv_bfloat162*)(hi + i);
    __nv_bfloat162* lp = (__nv_bfloat162*)(lo + i);
    hp[0] = __nv_bfloat162(h0, h1); hp[1] = __nv_bfloat162(h2, h3);
    lp[0] = __nv_bfloat162(l0, l1); lp[1] = __nv_bfloat162(l2, l3);
}

// ---------------------------------------------------------------------------
// HMMA bf16x3 GEMM: C[2048, N] = A[2048, 4096] * B[N, 4096]^T  (fp32 out)
// CTA 256x128, 8 warps (warp 64x64), BK=32, 3-stage cp.async pipeline.
// blockIdx.z selects B/C set (fused K+V projections).
// ---------------------------------------------------------------------------
#define BK 32
#define ASTR 40                              // bf16 elems per smem row
#define GT_A (256 * ASTR * 2)                // 20480 B
#define GT_B (128 * ASTR * 2)                // 10240 B
#define GSTAGE (2 * GT_A + 2 * GT_B)         // 61440 B
#define GNST 3
#define GSMEM (GNST * GSTAGE)                // 184320 B
#define KTILES (HID / BK)                    // 128

__global__ __launch_bounds__(256, 1) void gemm_mma_kernel(
    const __nv_bfloat16* __restrict__ Ah, const __nv_bfloat16* __restrict__ Al,
    const __nv_bfloat16* __restrict__ Bh0, const __nv_bfloat16* __restrict__ Bl0,
    float* __restrict__ C0,
    const __nv_bfloat16* __restrict__ Bh1, const __nv_bfloat16* __restrict__ Bl1,
    float* __restrict__ C1, int N)
{
    extern __shared__ char smem[];
    const uint32_t sb = smem_u32(smem);
    const int tid  = threadIdx.x;
    const int wid  = tid >> 5;
    const int lane = tid & 31;
    const int wm   = wid & 3;                // 4 m-tiles of 64
    const int wn   = wid >> 2;               // 2 n-tiles of 64
    const int m0   = blockIdx.y * 256;
    const int n0   = blockIdx.x * 128;

    const __nv_bfloat16* Bh = blockIdx.z ? Bh1 : Bh0;
    const __nv_bfloat16* Bl = blockIdx.z ? Bl1 : Bl0;
    float* C = blockIdx.z ? C1 : C0;

    const __nv_bfloat16* aS[2] = { Ah + (size_t)m0 * HID, Al + (size_t)m0 * HID };
    const __nv_bfloat16* bS[2] = { Bh + (size_t)n0 * HID, Bl + (size_t)n0 * HID };

    auto load_stage = [&](int kt, int stage) {
        const int kc = kt * BK;
        const uint32_t sbase = sb + stage * GSTAGE;
#pragma unroll
        for (int t = 0; t < 2; t++) {        // A hi, lo
            const uint32_t tb = sbase + t * GT_A;
#pragma unroll
            for (int i = 0; i < 4; i++) {
                int idx = tid + i * 256;     // 0..1023
                int row = idx >> 2, kch = idx & 3;
                cp_async16(tb + (uint32_t)(row * 80 + kch * 16),
                           aS[t] + (size_t)row * HID + kc + kch * 8);
            }
        }
#pragma unroll
        for (int t = 0; t < 2; t++) {        // B hi, lo
            const uint32_t tb = sbase + 2 * GT_A + t * GT_B;
#pragma unroll
            for (int i = 0; i < 2; i++) {
                int idx = tid + i * 256;     // 0..511
                int row = idx >> 2, kch = idx & 3;
                cp_async16(tb + (uint32_t)(row * 80 + kch * 16),
                           bS[t] + (size_t)row * HID + kc + kch * 8);
            }
        }
        asm volatile("cp.async.commit_group;" ::: "memory");
    };

    float acc[4][8][4];
#pragma unroll
    for (int i = 0; i < 4; i++)
#pragma unroll
        for (int j = 0; j < 8; j++)
#pragma unroll
            for (int q = 0; q < 4; q++) acc[i][j][q] = 0.0f;

    load_stage(0, 0);
    load_stage(1, 1);

    const int a_la  = lane & 15;
    const int a_k8  = (lane >> 4) << 3;
    const int b_r   = ((lane >> 4) << 3) + (lane & 7);   // paired-B row 0..15
    const int b_k8  = ((lane >> 3) & 1) << 3;

    for (int kt = 0; kt < KTILES; kt++) {
        if (kt + 2 < KTILES) {
            load_stage(kt + 2, (kt + 2) % GNST);
            asm volatile("cp.async.wait_group 2;" ::: "memory");
        } else {
            asm volatile("cp.async.wait_group 0;" ::: "memory");
        }
        __syncthreads();

        const uint32_t sbase = sb + (kt % GNST) * GSTAGE;
        const uint32_t sAh = sbase;
        const uint32_t sAl = sbase + GT_A;
        const uint32_t sBh = sbase + 2 * GT_A;
        const uint32_t sBl = sBh + GT_B;

#pragma unroll
        for (int k16 = 0; k16 < 2; k16++) {
            uint32_t ah[4][4], al[4][4], bh[4][4], bl[4][4];
#pragma unroll
            for (int i = 0; i < 4; i++) {
                int arow = wm * 64 + i * 16 + a_la;
                uint32_t off = (uint32_t)(arow * ASTR + k16 * 16 + a_k8) * 2;
                ldsm4(ah[i], sAh + off);
                ldsm4(al[i], sAl + off);
            }
#pragma unroll
            for (int jp = 0; jp < 4; jp++) {
                int brow = wn * 64 + jp * 16 + b_r;
                uint32_t off = (uint32_t)(brow * ASTR + k16 * 16 + b_k8) * 2;
                ldsm4(bh[jp], sBh + off);
                ldsm4(bl[jp], sBl + off);
            }
#pragma unroll
            for (int i = 0; i < 4; i++)
#pragma unroll
                for (int jp = 0; jp < 4; jp++) {
                    mma16816(acc[i][2 * jp],     ah[i], bh[jp]);
                    mma16816(acc[i][2 * jp],     ah[i], bl[jp]);
                    mma16816(acc[i][2 * jp],     al[i], bh[jp]);
                    mma16816(acc[i][2 * jp + 1], ah[i], bh[jp] + 2);
                    mma16816(acc[i][2 * jp + 1], ah[i], bl[jp] + 2);
                    mma16816(acc[i][2 * jp + 1], al[i], bh[jp] + 2);
                }
        }
        __syncthreads();
    }

#pragma unroll
    for (int i = 0; i < 4; i++) {
        int row = m0 + wm * 64 + i * 16 + (lane >> 2);
#pragma unroll
        for (int j = 0; j < 8; j++) {
            int col = n0 + wn * 64 + j * 8 + (lane & 3) * 2;
            *(float2*)&C[(size_t)row * N + col] =
                make_float2(acc[i][j][0], acc[i][j][1]);
            *(float2*)&C[(size_t)(row + 8) * N + col] =
                make_float2(acc[i][j][2], acc[i][j][3]);
        }
    }
}

// ---------------------------------------------------------------------------
// RoPE table (fp64, once)
// ---------------------------------------------------------------------------
__global__ void rope_table_kernel(const int* __restrict__ pos)
{
    int idx = blockIdx.x * blockDim.x + threadIdx.x;
    int s = idx >> 6, i = idx & 63;
    double inv = exp(-((double)(2 * i) / 128.0) * 9.210340371976184);
    double ang = (double)pos[s] * inv;
    g_cos[idx] = (float)cos(ang);
    g_sin[idx] = (float)sin(ang);
}

// ---------------------------------------------------------------------------
// Fused RoPE + scale(Q) + bf16 hi/lo split for Q and K.
// ---------------------------------------------------------------------------
__global__ void rope_split_kernel()
{
    const int s = blockIdx.x;
    const float qscale = 0.08838834764831845f;
    for (int idx = threadIdx.x; idx < (NH + NKV) * 64; idx += blockDim.x) {
        const float* src; __nv_bfloat16 *dh, *dl;
        int stride, head, i; float scale;
        if (idx < NH * 64) {
            src = g_Q; dh = g_Qh; dl = g_Ql; stride = HID;
            head = idx >> 6; i = idx & 63; scale = qscale;
        } else {
            int t = idx - NH * 64;
            src = g_K; dh = g_Kh; dl = g_Kl; stride = KVD;
            head = t >> 6; i = t & 63; scale = 1.0f;
        }
        float c  = g_cos[s * 64 + i];
        float sn = g_sin[s * 64 + i];
        size_t base = (size_t)s * stride + head * HD;
        float x0 = src[base + i];
        float x1 = src[base + i + 64];
        float y0 = (x0 * c - x1 * sn) * scale;
        float y1 = (x1 * c + x0 * sn) * scale;
        __nv_bfloat16 h0 = __float2bfloat16(y0);
        __nv_bfloat16 h1 = __float2bfloat16(y1);
        dh[base + i]      = h0;
        dh[base + i + 64] = h1;
        dl[base + i]      = __float2bfloat16(y0 - __bfloat162float(h0));
        dl[base + i + 64] = __float2bfloat16(y1 - __bfloat162float(h1));
    }
}

// ---------------------------------------------------------------------------
// Tensor-core flash attention. QK: Qh*Kh + Qh*Kl + Ql*Kh.
// PV: Ph*Vh + Ph*Vl + Pl*Vh  (V-lo REQUIRED: V error is coherent in output).
// CTA: 128 q-rows x 1 head, 8 warps, KV tile 64, double buffer.
// smem rows 136 bf16 (272B) -> conflict-free LDSM.
// ---------------------------------------------------------------------------
#define QSTR 136
#define FTILE (64 * QSTR * 2)        // 17408
#define FSTAGE (4 * FTILE)           // Kh, Kl, Vh, Vl = 69632
#define FQOFF  (2 * FSTAGE)          // 139264
#define FQSZ   (128 * QSTR * 2)      // 34816
#define FSMEM  (FQOFF + 2 * FQSZ)    // 208896

__global__ __launch_bounds__(256, 1) void flash_mma_kernel(
    const __nv_bfloat16* __restrict__ Qh, const __nv_bfloat16* __restrict__ Ql,
    const __nv_bfloat16* __restrict__ Kh, const __nv_bfloat16* __restrict__ Kl,
    const __nv_bfloat16* __restrict__ Vh, const __nv_bfloat16* __restrict__ Vl,
    float* __restrict__ O)
{
    extern __shared__ char smem[];
    const uint32_t sb = smem_u32(smem);
    const int tid = threadIdx.x;
    const int lane = tid & 31;
    const int w = tid >> 5;
    const int h = blockIdx.x;
    const int qb = gridDim.y - 1 - blockIdx.y;
    const int kvh = h >> 2;
    const int ntiles = 2 * (qb + 1);

    const __nv_bfloat16* qsrc[2] = {
        Qh + (size_t)(qb * 128) * HID + h * HD,
        Ql + (size_t)(qb * 128) * HID + h * HD };
    const __nv_bfloat16* tsrc[4] = {
        Kh + (size_t)kvh * HD, Kl + (size_t)kvh * HD,
        Vh + (size_t)kvh * HD, Vl + (size_t)kvh * HD };

#pragma unroll
    for (int s2 = 0; s2 < 2; s2++)
#pragma unroll
        for (int i = 0; i < 8; i++) {
            int idx = tid + i * 256;
            int row = idx >> 4, ch = idx & 15;
            cp_async16(sb + FQOFF + s2 * FQSZ + (uint32_t)(row * 272 + ch * 16),
                       qsrc[s2] + (size_t)row * HID + ch * 8);
        }
    asm volatile("cp.async.commit_group;" ::: "memory");

    auto load_tile = [&](int t, int buf) {
#pragma unroll
        for (int sub = 0; sub < 4; sub++) {
            const __nv_bfloat16* src = tsrc[sub];
            const uint32_t tb = sb + buf * FSTAGE + sub * FTILE;
#pragma unroll
            for (int i = 0; i < 4; i++) {
                int idx = tid + i * 256;
                int row = idx >> 4, ch = idx & 15;
                cp_async16(tb + (uint32_t)(row * 272 + ch * 16),
                           src + (size_t)(t * 64 + row) * KVD + ch * 8);
            }
        }
        asm volatile("cp.async.commit_group;" ::: "memory");
    };

    load_tile(0, 0);
    if (ntiles > 1) load_tile(1, 1);

    float m[2] = {-1e30f, -1e30f}, l[2] = {0.0f, 0.0f};
    float o[16][4];
#pragma unroll
    for (int j = 0; j < 16; j++)
#pragma unroll
        for (int q = 0; q < 4; q++) o[j][q] = 0.0f;

    const int a_la = lane & 15;
    const int a_k8 = (lane >> 4) << 3;
    const int b_r  = ((lane >> 4) << 3) + (lane & 7);   // paired-K row 0..15
    const int b_k8 = ((lane >> 3) & 1) << 3;
    const int r0 = lane >> 2;
    const int qrow0 = qb * 128 + w * 16;

    const uint32_t sQh = sb + FQOFF;
    const uint32_t sQl = sQh + FQSZ;

    for (int t = 0; t < ntiles; t++) {
        if (t + 1 < ntiles)
            asm volatile("cp.async.wait_group 1;" ::: "memory");
        else
            asm volatile("cp.async.wait_group 0;" ::: "memory");
        __syncthreads();

        const uint32_t stg = sb + (t & 1) * FSTAGE;
        const uint32_t sKh = stg, sKl = stg + FTILE;
        const uint32_t sVh = stg + 2 * FTILE, sVl = stg + 3 * FTILE;

        const bool skip = (qrow0 + 15) < t * 64;
        if (!skip) {
            // ---- S = Q K^T (3-term) ----
            float sc[8][4];
#pragma unroll
            for (int nt = 0; nt < 8; nt++)
#pragma unroll
                for (int q = 0; q < 4; q++) sc[nt][q] = 0.0f;

#pragma unroll
            for (int ks = 0; ks < 8; ks++) {
                uint32_t aoff = (uint32_t)((w * 16 + a_la) * QSTR + ks * 16 + a_k8) * 2;
                uint32_t aqh[4], aql[4];
                ldsm4(aqh, sQh + aoff);
                ldsm4(aql, sQl + aoff);
#pragma unroll
                for (int np = 0; np < 4; np++) {
                    uint32_t boff = (uint32_t)((np * 16 + b_r) * QSTR + ks * 16 + b_k8) * 2;
                    uint32_t bh[4], bl[4];
                    ldsm4(bh, sKh + boff);
                    ldsm4(bl, sKl + boff);
                    mma16816(sc[2 * np],     aqh, bh);
                    mma16816(sc[2 * np],     aqh, bl);
                    mma16816(sc[2 * np],     aql, bh);
                    mma16816(sc[2 * np + 1], aqh, bh + 2);
                    mma16816(sc[2 * np + 1], aqh, bl + 2);
                    mma16816(sc[2 * np + 1], aql, bh + 2);
                }
            }

            // ---- causal mask ----
            if (t * 64 + 63 > qrow0) {
#pragma unroll
                for (int nt = 0; nt < 8; nt++)
#pragma unroll
                    for (int e = 0; e < 4; e++) {
                        int col = t * 64 + nt * 8 + (lane & 3) * 2 + (e & 1);
                        int row = qrow0 + r0 + ((e >> 1) << 3);
                        if (col > row) sc[nt][e] = -1e30f;
                    }
            }

            // ---- online softmax ----
#pragma unroll
            for (int rr = 0; rr < 2; rr++) {
                float mt = -1e30f;
#pragma unroll
                for (int nt = 0; nt < 8; nt++)
                    mt = fmaxf(mt, fmaxf(sc[nt][rr * 2], sc[nt][rr * 2 + 1]));
                mt = fmaxf(mt, __shfl_xor_sync(0xffffffffu, mt, 1));
                mt = fmaxf(mt, __shfl_xor_sync(0xffffffffu, mt, 2));
                float mn = fmaxf(m[rr], mt);
                float alpha = __expf(m[rr] - mn);
                m[rr] = mn;
                float sum = 0.0f;
#pragma unroll
                for (int nt = 0; nt < 8; nt++) {
                    float p0 = __expf(sc[nt][rr * 2]     - mn);
                    float p1 = __expf(sc[nt][rr * 2 + 1] - mn);
                    sc[nt][rr * 2] = p0; sc[nt][rr * 2 + 1] = p1;
                    sum += p0 + p1;
                }
                sum += __shfl_xor_sync(0xffffffffu, sum, 1);
                sum += __shfl_xor_sync(0xffffffffu, sum, 2);
                l[rr] = l[rr] * alpha + sum;
#pragma unroll
                for (int j = 0; j < 16; j++) {
                    o[j][rr * 2]     *= alpha;
                    o[j][rr * 2 + 1] *= alpha;
                }
            }

            // ---- pack P hi/lo into A fragments ----
            uint32_t ph[4][4], pl[4][4];
#pragma unroll
            for (int ks2 = 0; ks2 < 4; ks2++)
#pragma unroll
                for (int half = 0; half < 2; half++) {
                    int nt = 2 * ks2 + half;
#pragma unroll
                    for (int rr = 0; rr < 2; rr++) {
                        float p0 = sc[nt][rr * 2], p1 = sc[nt][rr * 2 + 1];
                        __nv_bfloat16 h0 = __float2bfloat16(p0);
                        __nv_bfloat16 h1 = __float2bfloat16(p1);
                        ph[ks2][half * 2 + rr] =
                            (uint32_t)__bfloat16_as_ushort(h0) |
                            ((uint32_t)__bfloat16_as_ushort(h1) << 16);
                        pl[ks2][half * 2 + rr] =
                            pack_bf16(p0 - __bfloat162float(h0),
                                      p1 - __bfloat162float(h1));
                    }
                }

            // ---- O += P V (3-term) ----
#pragma unroll
            for (int ks2 = 0; ks2 < 4; ks2++) {
#pragma unroll
                for (int np = 0; np < 8; np++) {
                    uint32_t voff = (uint32_t)((ks2 * 16 + a_la) * QSTR + np * 16 + a_k8) * 2;
                    uint32_t vh[4], vl[4];
                    ldsm4t(vh, sVh + voff);
                    ldsm4t(vl, sVl + voff);
                    mma16816(o[2 * np],     ph[ks2], vh);
                    mma16816(o[2 * np],     ph[ks2], vl);
                    mma16816(o[2 * np],     pl[ks2], vh);
                    mma16816(o[2 * np + 1], ph[ks2], vh + 2);
                    mma16816(o[2 * np + 1], ph[ks2], vl + 2);
                    mma16816(o[2 * np + 1], pl[ks2], vh + 2);
                }
            }
        }
        __syncthreads();
        if (t + 2 < ntiles) load_tile(t + 2, t & 1);
    }

    // ---- epilogue ----
#pragma unroll
    for (int rr = 0; rr < 2; rr++) {
        float inv = 1.0f / l[rr];
        int grow = qrow0 + r0 + rr * 8;
#pragma unroll
        for (int j = 0; j < 16; j++) {
            int col = h * HD + j * 8 + (lane & 3) * 2;
            *(float2*)&O[(size_t)grow * HID + col] =
                make_float2(o[j][rr * 2] * inv, o[j][rr * 2 + 1] * inv);
        }
    }
}

// ---------------------------------------------------------------------------
// kernel_launch
// ---------------------------------------------------------------------------
extern "C" void kernel_launch(void* const* d_in, const int* in_sizes, int n_in,
                              void* d_out, int out_size)
{
    const float* hidden = (const float*)d_in[0];
    const int*   pos    = (const int*)d_in[1];
    const float* Wq     = (const float*)d_in[2];
    const float* Wk     = (const float*)d_in[3];
    const float* Wv     = (const float*)d_in[4];
    const float* Wo     = (const float*)d_in[5];
    float* out = (float*)d_out;

    float *qp, *kp, *vp, *aop;
    __nv_bfloat16 *ah, *al, *wh, *wl, *wh2, *wl2, *qhp, *qlp, *khp, *klp, *vhp, *vlp;
    cudaGetSymbolAddress((void**)&qp,  g_Q);
    cudaGetSymbolAddress((void**)&kp,  g_K);
    cudaGetSymbolAddress((void**)&vp,  g_V);
    cudaGetSymbolAddress((void**)&aop, g_AO);
    cudaGetSymbolAddress((void**)&ah,  g_Ah);
    cudaGetSymbolAddress((void**)&al,  g_Al);
    cudaGetSymbolAddress((void**)&wh,  g_Wh);
    cudaGetSymbolAddress((void**)&wl,  g_Wl);
    cudaGetSymbolAddress((void**)&wh2, g_Wh2);
    cudaGetSymbolAddress((void**)&wl2, g_Wl2);
    cudaGetSymbolAddress((void**)&qhp, g_Qh);
    cudaGetSymbolAddress((void**)&qlp, g_Ql);
    cudaGetSymbolAddress((void**)&khp, g_Kh);
    cudaGetSymbolAddress((void**)&klp, g_Kl);
    cudaGetSymbolAddress((void**)&vhp, g_Vh);
    cudaGetSymbolAddress((void**)&vlp, g_Vl);

    cudaFuncSetAttribute(gemm_mma_kernel,
                         cudaFuncAttributeMaxDynamicSharedMemorySize, GSMEM);
    cudaFuncSetAttribute(flash_mma_kernel,
                         cudaFuncAttributeMaxDynamicSharedMemorySize, FSMEM);

    const int NA  = S_LEN * HID;
    const int NWQ = HID * HID;
    const int NWK = KVD * HID;

    // activations + Q weight split, Q projection
    split_bf16_kernel<<<NA / 4 / 256, 256>>>(hidden, ah, al, NA);
    split_bf16_kernel<<<NWQ / 4 / 256, 256>>>(Wq, wh, wl, NWQ);
    gemm_mma_kernel<<<dim3(HID / 128, S_LEN / 256, 1), 256, GSMEM>>>(
        ah, al, wh, wl, qp, wh, wl, qp, HID);

    // K + V projections fused (z selects weight/output set)
    split_bf16_kernel<<<NWK / 4 / 256, 256>>>(Wk, wh, wl, NWK);
    split_bf16_kernel<<<NWK / 4 / 256, 256>>>(Wv, wh2, wl2, NWK);
    gemm_mma_kernel<<<dim3(KVD / 128, S_LEN / 256, 2), 256, GSMEM>>>(
        ah, al, wh, wl, kp, wh2, wl2, vp, KVD);

    // RoPE + splits
    rope_table_kernel<<<S_LEN * 64 / 256, 256>>>(pos);
    rope_split_kernel<<<S_LEN, 256>>>();
    split_bf16_kernel<<<S_LEN * KVD / 4 / 256, 256>>>(vp, vhp, vlp, S_LEN * KVD);

    // flash attention
    flash_mma_kernel<<<dim3(NH, S_LEN / 128), 256, FSMEM>>>(
        qhp, qlp, khp, klp, vhp, vlp, aop);

    // output projection
    split_bf16_kernel<<<NA / 4 / 256, 256>>>(aop, ah, al, NA);
    split_bf16_kernel<<<NWQ / 4 / 256, 256>>>(Wo, wh, wl, NWQ);
    gemm_mma_kernel<<<dim3(HID / 128, S_LEN / 256, 1), 256, GSMEM>>>(
        ah, al, wh, wl, out, wh, wl, out, HID);
}

// round 7
// speedup vs baseline: 4.6689x; 1.0092x over previous
#include <cuda_runtime.h>
#include <cuda_bf16.h>
#include <math.h>
#include <stdint.h>

#define S_LEN 2048
#define HID   4096
#define KVD   1024
#define NH    32
#define NKV   8
#define HD    128

// ---------------- scratch (device globals; allocation-free rule) -----------
__device__ float g_Q[S_LEN * HID];
__device__ float g_K[S_LEN * KVD];
__device__ float g_V[S_LEN * KVD];
__device__ float g_AO[S_LEN * HID];
__device__ __nv_bfloat16 g_Ah[S_LEN * HID];
__device__ __nv_bfloat16 g_Al[S_LEN * HID];
__device__ __nv_bfloat16 g_Wh[HID * HID];
__device__ __nv_bfloat16 g_Wl[HID * HID];
__device__ __nv_bfloat16 g_Wh2[KVD * HID];
__device__ __nv_bfloat16 g_Wl2[KVD * HID];
__device__ __nv_bfloat16 g_Qh[S_LEN * HID];
__device__ __nv_bfloat16 g_Ql[S_LEN * HID];
__device__ __nv_bfloat16 g_Kh[S_LEN * KVD];
__device__ __nv_bfloat16 g_Kl[S_LEN * KVD];
__device__ __nv_bfloat16 g_Vh[S_LEN * KVD];
__device__ __nv_bfloat16 g_Vl[S_LEN * KVD];
__device__ float g_cos[S_LEN * 64];
__device__ float g_sin[S_LEN * 64];

// ---------------- PTX helpers ----------------------------------------------
__device__ __forceinline__ uint32_t smem_u32(const void* p) {
    uint32_t a;
    asm("{ .reg .u64 t; cvta.to.shared.u64 t, %1; cvt.u32.u64 %0, t; }"
        : "=r"(a) : "l"(p));
    return a;
}
__device__ __forceinline__ void ldsm4(uint32_t* r, uint32_t addr) {
    asm volatile("ldmatrix.sync.aligned.m8n8.x4.shared.b16 {%0,%1,%2,%3}, [%4];"
                 : "=r"(r[0]), "=r"(r[1]), "=r"(r[2]), "=r"(r[3]) : "r"(addr));
}
__device__ __forceinline__ void ldsm4t(uint32_t* r, uint32_t addr) {
    asm volatile("ldmatrix.sync.aligned.m8n8.x4.trans.shared.b16 {%0,%1,%2,%3}, [%4];"
                 : "=r"(r[0]), "=r"(r[1]), "=r"(r[2]), "=r"(r[3]) : "r"(addr));
}
__device__ __forceinline__ void mma16816(float* d, const uint32_t* a,
                                         const uint32_t* b) {
    asm volatile(
        "mma.sync.aligned.m16n8k16.row.col.f32.bf16.bf16.f32 "
        "{%0,%1,%2,%3},{%4,%5,%6,%7},{%8,%9},{%0,%1,%2,%3};"
        : "+f"(d[0]), "+f"(d[1]), "+f"(d[2]), "+f"(d[3])
        : "r"(a[0]), "r"(a[1]), "r"(a[2]), "r"(a[3]), "r"(b[0]), "r"(b[1]));
}
__device__ __forceinline__ void cp_async16(uint32_t dst, const void* src) {
    asm volatile("cp.async.cg.shared.global [%0], [%1], 16;"
                 :: "r"(dst), "l"(src) : "memory");
}
__device__ __forceinline__ uint32_t pack_bf16(float x, float y) {
    uint32_t lo = (uint32_t)__bfloat16_as_ushort(__float2bfloat16(x));
    uint32_t hi = (uint32_t)__bfloat16_as_ushort(__float2bfloat16(y));
    return lo | (hi << 16);
}

// ---------------------------------------------------------------------------
// fp32 -> (bf16 hi, bf16 lo) split.
// ---------------------------------------------------------------------------
__global__ void split_bf16_kernel(const float* __restrict__ src,
                                  __nv_bfloat16* __restrict__ hi,
                                  __nv_bfloat16* __restrict__ lo, int n)
{
    int i = (blockIdx.x * blockDim.x + threadIdx.x) * 4;
    if (i >= n) return;
    float4 v = *(const float4*)(src + i);
    __nv_bfloat16 h0 = __float2bfloat16(v.x);
    __nv_bfloat16 h1 = __float2bfloat16(v.y);
    __nv_bfloat16 h2 = __float2bfloat16(v.z);
    __nv_bfloat16 h3 = __float2bfloat16(v.w);
    __nv_bfloat16 l0 = __float2bfloat16(v.x - __bfloat162float(h0));
    __nv_bfloat16 l1 = __float2bfloat16(v.y - __bfloat162float(h1));
    __nv_bfloat16 l2 = __float2bfloat16(v.z - __bfloat162float(h2));
    __nv_bfloat16 l3 = __float2bfloat16(v.w - __bfloat162float(h3));
    __nv_bfloat162* hp = (__nv_bfloat162*)(hi + i);
    __nv_bfloat162* lp = (__nv_bfloat162*)(lo + i);
    hp[0] = __nv_bfloat162(h0, h1); hp[1] = __nv_bfloat162(h2, h3);
    lp[0] = __nv_bfloat162(l0, l1); lp[1] = __nv_bfloat162(l2, l3);
}

// ---------------------------------------------------------------------------
// HMMA bf16x3 GEMM: C[2048, N] = A[2048, 4096] * B[N, 4096]^T  (fp32 out)
// CTA 256x128, 8 warps (warp 64x64), BK=32, 3-stage cp.async pipeline.
// Term-major MMA ordering (no dependent accumulator chains); 1 sync per kt.
// ---------------------------------------------------------------------------
#define BK 32
#define ASTR 40                              // bf16 elems per smem row
#define GT_A (256 * ASTR * 2)                // 20480 B
#define GT_B (128 * ASTR * 2)                // 10240 B
#define GSTAGE (2 * GT_A + 2 * GT_B)         // 61440 B
#define GNST 3
#define GSMEM (GNST * GSTAGE)                // 184320 B
#define KTILES (HID / BK)                    // 128

__global__ __launch_bounds__(256, 1) void gemm_mma_kernel(
    const __nv_bfloat16* __restrict__ Ah, const __nv_bfloat16* __restrict__ Al,
    const __nv_bfloat16* __restrict__ Bh0, const __nv_bfloat16* __restrict__ Bl0,
    float* __restrict__ C0,
    const __nv_bfloat16* __restrict__ Bh1, const __nv_bfloat16* __restrict__ Bl1,
    float* __restrict__ C1, int N)
{
    extern __shared__ char smem[];
    const uint32_t sb = smem_u32(smem);
    const int tid  = threadIdx.x;
    const int wid  = tid >> 5;
    const int lane = tid & 31;
    const int wm   = wid & 3;                // 4 m-tiles of 64
    const int wn   = wid >> 2;               // 2 n-tiles of 64
    const int m0   = blockIdx.y * 256;
    const int n0   = blockIdx.x * 128;

    const __nv_bfloat16* Bh = blockIdx.z ? Bh1 : Bh0;
    const __nv_bfloat16* Bl = blockIdx.z ? Bl1 : Bl0;
    float* C = blockIdx.z ? C1 : C0;

    const __nv_bfloat16* aS[2] = { Ah + (size_t)m0 * HID, Al + (size_t)m0 * HID };
    const __nv_bfloat16* bS[2] = { Bh + (size_t)n0 * HID, Bl + (size_t)n0 * HID };

    auto load_stage = [&](int kt, int stage) {
        const int kc = kt * BK;
        const uint32_t sbase = sb + stage * GSTAGE;
#pragma unroll
        for (int t = 0; t < 2; t++) {        // A hi, lo
            const uint32_t tb = sbase + t * GT_A;
#pragma unroll
            for (int i = 0; i < 4; i++) {
                int idx = tid + i * 256;     // 0..1023
                int row = idx >> 2, kch = idx & 3;
                cp_async16(tb + (uint32_t)(row * 80 + kch * 16),
                           aS[t] + (size_t)row * HID + kc + kch * 8);
            }
        }
#pragma unroll
        for (int t = 0; t < 2; t++) {        // B hi, lo
            const uint32_t tb = sbase + 2 * GT_A + t * GT_B;
#pragma unroll
            for (int i = 0; i < 2; i++) {
                int idx = tid + i * 256;     // 0..511
                int row = idx >> 2, kch = idx & 3;
                cp_async16(tb + (uint32_t)(row * 80 + kch * 16),
                           bS[t] + (size_t)row * HID + kc + kch * 8);
            }
        }
        asm volatile("cp.async.commit_group;" ::: "memory");
    };

    float acc[4][8][4];
#pragma unroll
    for (int i = 0; i < 4; i++)
#pragma unroll
        for (int j = 0; j < 8; j++)
#pragma unroll
            for (int q = 0; q < 4; q++) acc[i][j][q] = 0.0f;

    load_stage(0, 0);
    load_stage(1, 1);

    const int a_la  = lane & 15;
    const int a_k8  = (lane >> 4) << 3;
    const int b_r   = ((lane >> 4) << 3) + (lane & 7);   // paired-B row 0..15
    const int b_k8  = ((lane >> 3) & 1) << 3;

    for (int kt = 0; kt < KTILES; kt++) {
        if (kt + 1 < KTILES)
            asm volatile("cp.async.wait_group 1;" ::: "memory");
        else
            asm volatile("cp.async.wait_group 0;" ::: "memory");
        __syncthreads();
        // safe: stage (kt+2)%3 differs from stages kt%3 (this compute) and
        // (kt+1)%3 (in flight); all warps passed the sync -> kt-1 reads done.
        if (kt + 2 < KTILES) load_stage(kt + 2, (kt + 2) % GNST);

        const uint32_t sbase = sb + (kt % GNST) * GSTAGE;
        const uint32_t sAh = sbase;
        const uint32_t sAl = sbase + GT_A;
        const uint32_t sBh = sbase + 2 * GT_A;
        const uint32_t sBl = sBh + GT_B;

#pragma unroll
        for (int k16 = 0; k16 < 2; k16++) {
            uint32_t ah[4][4], al[4][4], bh[4][4], bl[4][4];
#pragma unroll
            for (int i = 0; i < 4; i++) {
                int arow = wm * 64 + i * 16 + a_la;
                uint32_t off = (uint32_t)(arow * ASTR + k16 * 16 + a_k8) * 2;
                ldsm4(ah[i], sAh + off);
                ldsm4(al[i], sAl + off);
            }
#pragma unroll
            for (int jp = 0; jp < 4; jp++) {
                int brow = wn * 64 + jp * 16 + b_r;
                uint32_t off = (uint32_t)(brow * ASTR + k16 * 16 + b_k8) * 2;
                ldsm4(bh[jp], sBh + off);
                ldsm4(bl[jp], sBl + off);
            }
            // term-major: all 32 accumulators per pass -> no RAW chains
#pragma unroll
            for (int i = 0; i < 4; i++)
#pragma unroll
                for (int jp = 0; jp < 4; jp++) {
                    mma16816(acc[i][2 * jp],     ah[i], bh[jp]);
                    mma16816(acc[i][2 * jp + 1], ah[i], bh[jp] + 2);
                }
#pragma unroll
            for (int i = 0; i < 4; i++)
#pragma unroll
                for (int jp = 0; jp < 4; jp++) {
                    mma16816(acc[i][2 * jp],     ah[i], bl[jp]);
                    mma16816(acc[i][2 * jp + 1], ah[i], bl[jp] + 2);
                }
#pragma unroll
            for (int i = 0; i < 4; i++)
#pragma unroll
                for (int jp = 0; jp < 4; jp++) {
                    mma16816(acc[i][2 * jp],     al[i], bh[jp]);
                    mma16816(acc[i][2 * jp + 1], al[i], bh[jp] + 2);
                }
        }
    }

#pragma unroll
    for (int i = 0; i < 4; i++) {
        int row = m0 + wm * 64 + i * 16 + (lane >> 2);
#pragma unroll
        for (int j = 0; j < 8; j++) {
            int col = n0 + wn * 64 + j * 8 + (lane & 3) * 2;
            *(float2*)&C[(size_t)row * N + col] =
                make_float2(acc[i][j][0], acc[i][j][1]);
            *(float2*)&C[(size_t)(row + 8) * N + col] =
                make_float2(acc[i][j][2], acc[i][j][3]);
        }
    }
}

// ---------------------------------------------------------------------------
// RoPE table (fp64, once)
// ---------------------------------------------------------------------------
__global__ void rope_table_kernel(const int* __restrict__ pos)
{
    int idx = blockIdx.x * blockDim.x + threadIdx.x;
    int s = idx >> 6, i = idx & 63;
    double inv = exp(-((double)(2 * i) / 128.0) * 9.210340371976184);
    double ang = (double)pos[s] * inv;
    g_cos[idx] = (float)cos(ang);
    g_sin[idx] = (float)sin(ang);
}

// ---------------------------------------------------------------------------
// Fused RoPE + scale(Q) + bf16 hi/lo split for Q and K.
// ---------------------------------------------------------------------------
__global__ void rope_split_kernel()
{
    const int s = blockIdx.x;
    const float qscale = 0.08838834764831845f;
    for (int idx = threadIdx.x; idx < (NH + NKV) * 64; idx += blockDim.x) {
        const float* src; __nv_bfloat16 *dh, *dl;
        int stride, head, i; float scale;
        if (idx < NH * 64) {
            src = g_Q; dh = g_Qh; dl = g_Ql; stride = HID;
            head = idx >> 6; i = idx & 63; scale = qscale;
        } else {
            int t = idx - NH * 64;
            src = g_K; dh = g_Kh; dl = g_Kl; stride = KVD;
            head = t >> 6; i = t & 63; scale = 1.0f;
        }
        float c  = g_cos[s * 64 + i];
        float sn = g_sin[s * 64 + i];
        size_t base = (size_t)s * stride + head * HD;
        float x0 = src[base + i];
        float x1 = src[base + i + 64];
        float y0 = (x0 * c - x1 * sn) * scale;
        float y1 = (x1 * c + x0 * sn) * scale;
        __nv_bfloat16 h0 = __float2bfloat16(y0);
        __nv_bfloat16 h1 = __float2bfloat16(y1);
        dh[base + i]      = h0;
        dh[base + i + 64] = h1;
        dl[base + i]      = __float2bfloat16(y0 - __bfloat162float(h0));
        dl[base + i + 64] = __float2bfloat16(y1 - __bfloat162float(h1));
    }
}

// ---------------------------------------------------------------------------
// Tensor-core flash attention. QK: Qh*Kh + Qh*Kl + Ql*Kh (term-major).
// PV: Ph*Vh + Ph*Vl + Pl*Vh (term-major, 4-np blocks).
// CTA: 128 q-rows x 1 head, 8 warps, KV tile 64, double buffer.
// ---------------------------------------------------------------------------
#define QSTR 136
#define FTILE (64 * QSTR * 2)        // 17408
#define FSTAGE (4 * FTILE)           // Kh, Kl, Vh, Vl = 69632
#define FQOFF  (2 * FSTAGE)          // 139264
#define FQSZ   (128 * QSTR * 2)      // 34816
#define FSMEM  (FQOFF + 2 * FQSZ)    // 208896

__global__ __launch_bounds__(256, 1) void flash_mma_kernel(
    const __nv_bfloat16* __restrict__ Qh, const __nv_bfloat16* __restrict__ Ql,
    const __nv_bfloat16* __restrict__ Kh, const __nv_bfloat16* __restrict__ Kl,
    const __nv_bfloat16* __restrict__ Vh, const __nv_bfloat16* __restrict__ Vl,
    float* __restrict__ O)
{
    extern __shared__ char smem[];
    const uint32_t sb = smem_u32(smem);
    const int tid = threadIdx.x;
    const int lane = tid & 31;
    const int w = tid >> 5;
    const int h = blockIdx.x;
    const int qb = gridDim.y - 1 - blockIdx.y;
    const int kvh = h >> 2;
    const int ntiles = 2 * (qb + 1);

    const __nv_bfloat16* qsrc[2] = {
        Qh + (size_t)(qb * 128) * HID + h * HD,
        Ql + (size_t)(qb * 128) * HID + h * HD };
    const __nv_bfloat16* tsrc[4] = {
        Kh + (size_t)kvh * HD, Kl + (size_t)kvh * HD,
        Vh + (size_t)kvh * HD, Vl + (size_t)kvh * HD };

#pragma unroll
    for (int s2 = 0; s2 < 2; s2++)
#pragma unroll
        for (int i = 0; i < 8; i++) {
            int idx = tid + i * 256;
            int row = idx >> 4, ch = idx & 15;
            cp_async16(sb + FQOFF + s2 * FQSZ + (uint32_t)(row * 272 + ch * 16),
                       qsrc[s2] + (size_t)row * HID + ch * 8);
        }
    asm volatile("cp.async.commit_group;" ::: "memory");

    auto load_tile = [&](int t, int buf) {
#pragma unroll
        for (int sub = 0; sub < 4; sub++) {
            const __nv_bfloat16* src = tsrc[sub];
            const uint32_t tb = sb + buf * FSTAGE + sub * FTILE;
#pragma unroll
            for (int i = 0; i < 4; i++) {
                int idx = tid + i * 256;
                int row = idx >> 4, ch = idx & 15;
                cp_async16(tb + (uint32_t)(row * 272 + ch * 16),
                           src + (size_t)(t * 64 + row) * KVD + ch * 8);
            }
        }
        asm volatile("cp.async.commit_group;" ::: "memory");
    };

    load_tile(0, 0);
    if (ntiles > 1) load_tile(1, 1);

    float m[2] = {-1e30f, -1e30f}, l[2] = {0.0f, 0.0f};
    float o[16][4];
#pragma unroll
    for (int j = 0; j < 16; j++)
#pragma unroll
        for (int q = 0; q < 4; q++) o[j][q] = 0.0f;

    const int a_la = lane & 15;
    const int a_k8 = (lane >> 4) << 3;
    const int b_r  = ((lane >> 4) << 3) + (lane & 7);
    const int b_k8 = ((lane >> 3) & 1) << 3;
    const int r0 = lane >> 2;
    const int qrow0 = qb * 128 + w * 16;

    const uint32_t sQh = sb + FQOFF;
    const uint32_t sQl = sQh + FQSZ;

    for (int t = 0; t < ntiles; t++) {
        if (t + 1 < ntiles)
            asm volatile("cp.async.wait_group 1;" ::: "memory");
        else
            asm volatile("cp.async.wait_group 0;" ::: "memory");
        __syncthreads();

        const uint32_t stg = sb + (t & 1) * FSTAGE;
        const uint32_t sKh = stg, sKl = stg + FTILE;
        const uint32_t sVh = stg + 2 * FTILE, sVl = stg + 3 * FTILE;

        const bool skip = (qrow0 + 15) < t * 64;
        if (!skip) {
            // ---- S = Q K^T (3-term, term-major per ks) ----
            float sc[8][4];
#pragma unroll
            for (int nt = 0; nt < 8; nt++)
#pragma unroll
                for (int q = 0; q < 4; q++) sc[nt][q] = 0.0f;

#pragma unroll
            for (int ks = 0; ks < 8; ks++) {
                uint32_t aoff = (uint32_t)((w * 16 + a_la) * QSTR + ks * 16 + a_k8) * 2;
                uint32_t aqh[4], aql[4];
                ldsm4(aqh, sQh + aoff);
                ldsm4(aql, sQl + aoff);
                uint32_t bh[4][4], bl[4][4];
#pragma unroll
                for (int np = 0; np < 4; np++) {
                    uint32_t boff = (uint32_t)((np * 16 + b_r) * QSTR + ks * 16 + b_k8) * 2;
                    ldsm4(bh[np], sKh + boff);
                    ldsm4(bl[np], sKl + boff);
                }
#pragma unroll
                for (int np = 0; np < 4; np++) {
                    mma16816(sc[2 * np],     aqh, bh[np]);
                    mma16816(sc[2 * np + 1], aqh, bh[np] + 2);
                }
#pragma unroll
                for (int np = 0; np < 4; np++) {
                    mma16816(sc[2 * np],     aqh, bl[np]);
                    mma16816(sc[2 * np + 1], aqh, bl[np] + 2);
                }
#pragma unroll
                for (int np = 0; np < 4; np++) {
                    mma16816(sc[2 * np],     aql, bh[np]);
                    mma16816(sc[2 * np + 1], aql, bh[np] + 2);
                }
            }

            // ---- causal mask ----
            if (t * 64 + 63 > qrow0) {
#pragma unroll
                for (int nt = 0; nt < 8; nt++)
#pragma unroll
                    for (int e = 0; e < 4; e++) {
                        int col = t * 64 + nt * 8 + (lane & 3) * 2 + (e & 1);
                        int row = qrow0 + r0 + ((e >> 1) << 3);
                        if (col > row) sc[nt][e] = -1e30f;
                    }
            }

            // ---- online softmax ----
#pragma unroll
            for (int rr = 0; rr < 2; rr++) {
                float mt = -1e30f;
#pragma unroll
                for (int nt = 0; nt < 8; nt++)
                    mt = fmaxf(mt, fmaxf(sc[nt][rr * 2], sc[nt][rr * 2 + 1]));
                mt = fmaxf(mt, __shfl_xor_sync(0xffffffffu, mt, 1));
                mt = fmaxf(mt, __shfl_xor_sync(0xffffffffu, mt, 2));
                float mn = fmaxf(m[rr], mt);
                float alpha = __expf(m[rr] - mn);
                m[rr] = mn;
                float sum = 0.0f;
#pragma unroll
                for (int nt = 0; nt < 8; nt++) {
                    float p0 = __expf(sc[nt][rr * 2]     - mn);
                    float p1 = __expf(sc[nt][rr * 2 + 1] - mn);
                    sc[nt][rr * 2] = p0; sc[nt][rr * 2 + 1] = p1;
                    sum += p0 + p1;
                }
                sum += __shfl_xor_sync(0xffffffffu, sum, 1);
                sum += __shfl_xor_sync(0xffffffffu, sum, 2);
                l[rr] = l[rr] * alpha + sum;
#pragma unroll
                for (int j = 0; j < 16; j++) {
                    o[j][rr * 2]     *= alpha;
                    o[j][rr * 2 + 1] *= alpha;
                }
            }

            // ---- pack P hi/lo into A fragments ----
            uint32_t ph[4][4], pl[4][4];
#pragma unroll
            for (int ks2 = 0; ks2 < 4; ks2++)
#pragma unroll
                for (int half = 0; half < 2; half++) {
                    int nt = 2 * ks2 + half;
#pragma unroll
                    for (int rr = 0; rr < 2; rr++) {
                        float p0 = sc[nt][rr * 2], p1 = sc[nt][rr * 2 + 1];
                        __nv_bfloat16 h0 = __float2bfloat16(p0);
                        __nv_bfloat16 h1 = __float2bfloat16(p1);
                        ph[ks2][half * 2 + rr] =
                            (uint32_t)__bfloat16_as_ushort(h0) |
                            ((uint32_t)__bfloat16_as_ushort(h1) << 16);
                        pl[ks2][half * 2 + rr] =
                            pack_bf16(p0 - __bfloat162float(h0),
                                      p1 - __bfloat162float(h1));
                    }
                }

            // ---- O += P V (3-term, term-major in 4-np blocks) ----
#pragma unroll
            for (int ks2 = 0; ks2 < 4; ks2++) {
#pragma unroll
                for (int g = 0; g < 2; g++) {
                    uint32_t vh[4][4], vl[4][4];
#pragma unroll
                    for (int q = 0; q < 4; q++) {
                        int np = g * 4 + q;
                        uint32_t voff = (uint32_t)((ks2 * 16 + a_la) * QSTR + np * 16 + a_k8) * 2;
                        ldsm4t(vh[q], sVh + voff);
                        ldsm4t(vl[q], sVl + voff);
                    }
#pragma unroll
                    for (int q = 0; q < 4; q++) {
                        int np = g * 4 + q;
                        mma16816(o[2 * np],     ph[ks2], vh[q]);
                        mma16816(o[2 * np + 1], ph[ks2], vh[q] + 2);
                    }
#pragma unroll
                    for (int q = 0; q < 4; q++) {
                        int np = g * 4 + q;
                        mma16816(o[2 * np],     ph[ks2], vl[q]);
                        mma16816(o[2 * np + 1], ph[ks2], vl[q] + 2);
                    }
#pragma unroll
                    for (int q = 0; q < 4; q++) {
                        int np = g * 4 + q;
                        mma16816(o[2 * np],     pl[ks2], vh[q]);
                        mma16816(o[2 * np + 1], pl[ks2], vh[q] + 2);
                    }
                }
            }
        }
        __syncthreads();
        if (t + 2 < ntiles) load_tile(t + 2, t & 1);
    }

    // ---- epilogue ----
#pragma unroll
    for (int rr = 0; rr < 2; rr++) {
        float inv = 1.0f / l[rr];
        int grow = qrow0 + r0 + rr * 8;
#pragma unroll
        for (int j = 0; j < 16; j++) {
            int col = h * HD + j * 8 + (lane & 3) * 2;
            *(float2*)&O[(size_t)grow * HID + col] =
                make_float2(o[j][rr * 2] * inv, o[j][rr * 2 + 1] * inv);
        }
    }
}

// ---------------------------------------------------------------------------
// kernel_launch
// ---------------------------------------------------------------------------
extern "C" void kernel_launch(void* const* d_in, const int* in_sizes, int n_in,
                              void* d_out, int out_size)
{
    const float* hidden = (const float*)d_in[0];
    const int*   pos    = (const int*)d_in[1];
    const float* Wq     = (const float*)d_in[2];
    const float* Wk     = (const float*)d_in[3];
    const float* Wv     = (const float*)d_in[4];
    const float* Wo     = (const float*)d_in[5];
    float* out = (float*)d_out;

    float *qp, *kp, *vp, *aop;
    __nv_bfloat16 *ah, *al, *wh, *wl, *wh2, *wl2, *qhp, *qlp, *khp, *klp, *vhp, *vlp;
    cudaGetSymbolAddress((void**)&qp,  g_Q);
    cudaGetSymbolAddress((void**)&kp,  g_K);
    cudaGetSymbolAddress((void**)&vp,  g_V);
    cudaGetSymbolAddress((void**)&aop, g_AO);
    cudaGetSymbolAddress((void**)&ah,  g_Ah);
    cudaGetSymbolAddress((void**)&al,  g_Al);
    cudaGetSymbolAddress((void**)&wh,  g_Wh);
    cudaGetSymbolAddress((void**)&wl,  g_Wl);
    cudaGetSymbolAddress((void**)&wh2, g_Wh2);
    cudaGetSymbolAddress((void**)&wl2, g_Wl2);
    cudaGetSymbolAddress((void**)&qhp, g_Qh);
    cudaGetSymbolAddress((void**)&qlp, g_Ql);
    cudaGetSymbolAddress((void**)&khp, g_Kh);
    cudaGetSymbolAddress((void**)&klp, g_Kl);
    cudaGetSymbolAddress((void**)&vhp, g_Vh);
    cudaGetSymbolAddress((void**)&vlp, g_Vl);

    cudaFuncSetAttribute(gemm_mma_kernel,
                         cudaFuncAttributeMaxDynamicSharedMemorySize, GSMEM);
    cudaFuncSetAttribute(flash_mma_kernel,
                         cudaFuncAttributeMaxDynamicSharedMemorySize, FSMEM);

    const int NA  = S_LEN * HID;
    const int NWQ = HID * HID;
    const int NWK = KVD * HID;

    // activations + Q weight split, Q projection
    split_bf16_kernel<<<NA / 4 / 256, 256>>>(hidden, ah, al, NA);
    split_bf16_kernel<<<NWQ / 4 / 256, 256>>>(Wq, wh, wl, NWQ);
    gemm_mma_kernel<<<dim3(HID / 128, S_LEN / 256, 1), 256, GSMEM>>>(
        ah, al, wh, wl, qp, wh, wl, qp, HID);

    // K + V projections fused (z selects weight/output set)
    split_bf16_kernel<<<NWK / 4 / 256, 256>>>(Wk, wh, wl, NWK);
    split_bf16_kernel<<<NWK / 4 / 256, 256>>>(Wv, wh2, wl2, NWK);
    gemm_mma_kernel<<<dim3(KVD / 128, S_LEN / 256, 2), 256, GSMEM>>>(
        ah, al, wh, wl, kp, wh2, wl2, vp, KVD);

    // RoPE + splits
    rope_table_kernel<<<S_LEN * 64 / 256, 256>>>(pos);
    rope_split_kernel<<<S_LEN, 256>>>();
    split_bf16_kernel<<<S_LEN * KVD / 4 / 256, 256>>>(vp, vhp, vlp, S_LEN * KVD);

    // flash attention
    flash_mma_kernel<<<dim3(NH, S_LEN / 128), 256, FSMEM>>>(
        qhp, qlp, khp, klp, vhp, vlp, aop);

    // output projection
    split_bf16_kernel<<<NA / 4 / 256, 256>>>(aop, ah, al, NA);
    split_bf16_kernel<<<NWQ / 4 / 256, 256>>>(Wo, wh, wl, NWQ);
    gemm_mma_kernel<<<dim3(HID / 128, S_LEN / 256, 1), 256, GSMEM>>>(
        ah, al, wh, wl, out, wh, wl, out, HID);
}